// round 4
// baseline (speedup 1.0000x reference)
#include <cuda_runtime.h>
#include <math.h>

#define S_T 100
#define B_N 128
#define D_N 512
#define SM_N 64
#define M_N (S_T*B_N)
#define EPSG 1e-20f

// ------------------------- device scratch (no allocs allowed) -------------
__device__ float    g_e[M_N*D_N];          // summed embeddings [m][512], m=s*128+b
__device__ float    g_Xl[(size_t)M_N*2048];// e@Wih_l^T + biases, permuted cols (d*4+q)
__device__ float    g_Xs[M_N*256];         // e@Wih_s^T + biases, natural cols (q*64+d)
__device__ float    g_pe[M_N*2];           // e-part of gate logits + b_gate
__device__ unsigned g_Wih_u[D_N*2048];     // tf32-packed [k][d*4+q]
__device__ unsigned g_Whh_u[D_N*2048];     // tf32-packed [k][d*4+q]
__device__ unsigned g_Wihs_u[D_N*256];     // tf32-packed [k][q*64+d]
__device__ float    g_bias_l[2048];
__device__ float    g_bias_s[256];
__device__ float    g_hlp[2][B_N*D_N];     // h_l'(t), parity t&1
__device__ float    g_clp[B_N*D_N];        // c_l'(t), single buffer (owner-local RMW)
__device__ float    g_hnew[2][B_N*D_N];    // H(t) written at step t to buf t&1
__device__ float    g_hs[2][B_N*SM_N];     // small-LSTM h_s2(t)
__device__ float    g_cs[2][B_N*SM_N];
__device__ float    g_ppart[2][64*B_N*2];  // gate-logit partials per n-tile

// ------------------------- helpers ----------------------------------------
__device__ __forceinline__ unsigned f2t(float x){
    unsigned r; asm("cvt.rna.tf32.f32 %0, %1;" : "=r"(r) : "f"(x)); return r;
}
__device__ __forceinline__ void mma8(float* c, unsigned a0, unsigned a1, unsigned a2,
                                     unsigned a3, unsigned b0, unsigned b1){
    asm volatile(
      "mma.sync.aligned.m16n8k8.row.col.f32.tf32.tf32.f32 "
      "{%0,%1,%2,%3},{%4,%5,%6,%7},{%8,%9},{%0,%1,%2,%3};\n"
      : "+f"(c[0]), "+f"(c[1]), "+f"(c[2]), "+f"(c[3])
      : "r"(a0), "r"(a1), "r"(a2), "r"(a3), "r"(b0), "r"(b1));
}
__device__ __forceinline__ float sigf(float x){ return 1.f/(1.f+__expf(-x)); }

// ------------------------- 1) embedding gather-sum -------------------------
__global__ void k_embed(const int* __restrict__ x, const float* __restrict__ emb){
    int m = blockIdx.x;            // m = s*128 + b
    int s = m >> 7, b = m & 127;
    const int* codes = x + (b*S_T + s)*16;
    int d = threadIdx.x * 4;
    float4 acc = make_float4(0.f,0.f,0.f,0.f);
    #pragma unroll
    for (int n = 0; n < 16; n++){
        int c = codes[n];
        float4 v = *reinterpret_cast<const float4*>(emb + (size_t)c*D_N + d);
        acc.x += v.x; acc.y += v.y; acc.z += v.z; acc.w += v.w;
    }
    *reinterpret_cast<float4*>(g_e + (size_t)m*D_N + d) = acc;
}

// ------------------------- 2) weight repack (tf32 + permute) ---------------
__global__ void k_repack(const float* __restrict__ wihl, const float* __restrict__ whhl,
                         const float* __restrict__ bihl, const float* __restrict__ bhhl,
                         const float* __restrict__ wihs, const float* __restrict__ bihs,
                         const float* __restrict__ bhhs){
    long idx = (long)blockIdx.x*256 + threadIdx.x;
    if (blockIdx.x < 4096){                      // Whh: out[k*2048 + d*4+q]
        int k = (int)(idx >> 11), n = (int)(idx & 2047);
        int q = n & 3, dd = n >> 2;
        g_Whh_u[idx] = f2t(whhl[(size_t)(q*512+dd)*512 + k]);
    } else if (blockIdx.x < 8192){               // Wih
        long i = idx - 2048L*512;
        int k = (int)(i >> 11), n = (int)(i & 2047);
        int q = n & 3, dd = n >> 2;
        g_Wih_u[i] = f2t(wihl[(size_t)(q*512+dd)*512 + k]);
    } else if (blockIdx.x < 8704){               // Wihs: out[k*256 + n], n natural
        long i = idx - 2L*2048*512;
        int k = (int)(i >> 8), n = (int)(i & 255);
        g_Wihs_u[i] = f2t(wihs[(size_t)n*512 + k]);
    } else if (blockIdx.x < 8712){               // bias_l (permuted)
        int n = (int)(idx - (2L*2048*512 + 512L*256));
        int q = n & 3, dd = n >> 2;
        g_bias_l[n] = bihl[q*512+dd] + bhhl[q*512+dd];
    } else {
        int n = threadIdx.x;
        g_bias_s[n] = bihs[n] + bhhs[n];
    }
}

// ------------------------- 3) input GEMMs (tf32 mma) -----------------------
// C[M,N] = g_e[M,512] @ Bp[512,N] + bias[N].  CTA tile 128x64, K chunks of 128.
__global__ void k_gemm(int mode){
    extern __shared__ float sm[];
    float*    As = sm;                                 // [128][132]
    unsigned* Bs = (unsigned*)(sm + 128*132);          // [128][72]
    const unsigned* Bp = mode ? g_Wihs_u : g_Wih_u;
    const float* bias  = mode ? g_bias_s : g_bias_l;
    float* C           = mode ? g_Xs    : g_Xl;
    const int N        = mode ? 256     : 2048;
    int bm = blockIdx.x, bn = blockIdx.y;
    int tid = threadIdx.x, wv = tid >> 5, lane = tid & 31;
    int fr = lane >> 2, fc = lane & 3;
    float acc[8][4];
    #pragma unroll
    for (int i = 0; i < 8; i++){
        #pragma unroll
        for (int j = 0; j < 4; j++) acc[i][j] = 0.f;
    }
    for (int kc = 0; kc < 4; kc++){
        for (int i = 0; i < 64; i++){
            int e = i*256 + tid;
            int r = e >> 7, c = e & 127;
            As[r*132 + c] = g_e[(size_t)(bm*128 + r)*512 + kc*128 + c];
        }
        for (int i = 0; i < 32; i++){
            int e = i*256 + tid;
            int k = e >> 6, n = e & 63;
            Bs[k*72 + n] = Bp[(size_t)(kc*128 + k)*N + bn*64 + n];
        }
        __syncthreads();
        #pragma unroll
        for (int ks = 0; ks < 16; ks++){
            int kk = ks*8;
            unsigned a0 = f2t(As[(wv*16 + fr    )*132 + kk + fc    ]);
            unsigned a1 = f2t(As[(wv*16 + fr + 8)*132 + kk + fc    ]);
            unsigned a2 = f2t(As[(wv*16 + fr    )*132 + kk + fc + 4]);
            unsigned a3 = f2t(As[(wv*16 + fr + 8)*132 + kk + fc + 4]);
            #pragma unroll
            for (int nf = 0; nf < 8; nf++){
                unsigned b0 = Bs[(kk + fc    )*72 + nf*8 + fr];
                unsigned b1 = Bs[(kk + fc + 4)*72 + nf*8 + fr];
                mma8(acc[nf], a0, a1, a2, a3, b0, b1);
            }
        }
        __syncthreads();
    }
    #pragma unroll
    for (int nf = 0; nf < 8; nf++){
        int row = bm*128 + wv*16 + fr;
        int col = bn*64 + nf*8 + fc*2;
        float b0 = bias[col], b1 = bias[col+1];
        C[(size_t)row*N + col]       = acc[nf][0] + b0;
        C[(size_t)row*N + col + 1]   = acc[nf][1] + b1;
        C[(size_t)(row+8)*N + col]   = acc[nf][2] + b0;
        C[(size_t)(row+8)*N + col+1] = acc[nf][3] + b1;
    }
}

// ------------------------- 4) e-part of gate logits ------------------------
__global__ void k_pe(const float* __restrict__ wg, const float* __restrict__ bg){
    int gw = blockIdx.x*8 + (threadIdx.x >> 5);
    int lane = threadIdx.x & 31;
    int stride = gridDim.x*8;
    for (int m = gw; m < M_N; m += stride){
        float s0 = 0.f, s1 = 0.f;
        for (int k = lane; k < 512; k += 32){
            float ev = g_e[(size_t)m*512 + k];
            s0 += ev*wg[k];
            s1 += ev*wg[1536 + k];
        }
        #pragma unroll
        for (int o = 16; o > 0; o >>= 1){
            s0 += __shfl_xor_sync(0xffffffffu, s0, o);
            s1 += __shfl_xor_sync(0xffffffffu, s1, o);
        }
        if (lane == 0){ g_pe[m*2] = s0 + bg[0]; g_pe[m*2+1] = s1 + bg[1]; }
    }
}

// ------------------------- 5) per-step kernel ------------------------------
// blocks 0..63: recurrent GEMM (32 permuted cols = 8 hidden dims each) + cell
// blocks 64..71: small LSTM (16 batch rows each)
__global__ void k_step(int t, const float* __restrict__ gum, const float* __restrict__ wg,
                       const float* __restrict__ whs_g){
    extern __shared__ float sm[];
    int tid = threadIdx.x;
    int w = t & 1, rb = 1 - w;

    if (blockIdx.x >= 64){
        // ---- small LSTM ----
        float* whs = sm;                // [256][65]
        float* hss = sm + 256*65;       // [16][64]
        float* css = hss + 16*64;       // [16][64]
        int cta = blockIdx.x - 64;
        int b0 = cta*16;
        for (int i = tid; i < 256*64; i += 256)
            whs[(i>>6)*65 + (i&63)] = whs_g[i];
        for (int i = tid; i < 16*64; i += 256){
            int bl = i >> 6, k = i & 63;
            hss[i] = t ? g_hs[rb][(b0+bl)*64 + k] : 0.f;
            css[i] = t ? g_cs[rb][(b0+bl)*64 + k] : 0.f;
        }
        __syncthreads();
        int d = tid & 63, blb = tid >> 6;
        for (int i = 0; i < 4; i++){
            int bl = blb + i*4;
            int b = b0 + bl;
            size_t xb = (size_t)(t*128 + b)*256;
            float gi = g_Xs[xb + d];
            float gf = g_Xs[xb + 64 + d];
            float gg = g_Xs[xb + 128 + d];
            float go = g_Xs[xb + 192 + d];
            for (int k = 0; k < 64; k++){
                float h = hss[bl*64 + k];
                gi += h*whs[(d      )*65 + k];
                gf += h*whs[(64  + d)*65 + k];
                gg += h*whs[(128 + d)*65 + k];
                go += h*whs[(192 + d)*65 + k];
            }
            float cp = css[bl*64 + d];
            float c2 = sigf(gf)*cp + sigf(gi)*tanhf(gg);
            float h2 = sigf(go)*tanhf(c2);
            g_hs[w][b*64 + d] = h2;
            g_cs[w][b*64 + d] = c2;
        }
        return;
    }

    // ---- recurrent GEMM CTA ----
    float*    As  = sm;                                 // [128][132]
    unsigned* Bs  = (unsigned*)(sm + 128*132);          // [128][40]
    float*    r0s = sm + 128*132 + 128*40;
    float*    r1s = r0s + 128;
    float*    gsc = r1s + 128;                          // 8 x [16][33]
    int ct = blockIdx.x;
    int wv = tid >> 5, lane = tid & 31;
    int fr = lane >> 2, fc = lane & 3;
    int dlo = ct*8, dhi = dlo + 8;

    if (t > 0 && tid < 128){
        int b = tid;
        float y0 = g_pe[((t-1)*128 + b)*2];
        float y1 = g_pe[((t-1)*128 + b)*2 + 1];
        for (int j = 0; j < 64; j++){
            y0 += g_ppart[rb][(j*128 + b)*2];
            y1 += g_ppart[rb][(j*128 + b)*2 + 1];
        }
        float u0 = gum[((t-1)*128 + b)*2];
        float u1 = gum[((t-1)*128 + b)*2 + 1];
        y0 -= logf(-logf(u0 + EPSG) + EPSG);
        y1 -= logf(-logf(u1 + EPSG) + EPSG);
        float mx = fmaxf(y0, y1);
        float e0 = __expf(y0 - mx), e1 = __expf(y1 - mx);
        float r0 = e0/(e0 + e1);
        r0s[b] = r0; r1s[b] = 1.f - r0;
    }
    __syncthreads();

    float acc[4][4];
    #pragma unroll
    for (int i = 0; i < 4; i++){
        #pragma unroll
        for (int j = 0; j < 4; j++) acc[i][j] = 0.f;
    }

    for (int kc = 0; kc < 4; kc++){
        // build A chunk = H(t)[:, kc*128 : kc*128+128] in fp32
        for (int i = 0; i < 64; i++){
            int e = i*256 + tid;
            int b = e >> 7, kk = e & 127;
            int k = kc*128 + kk;
            float val;
            if (t == 0) val = 0.f;
            else {
                float hl  = g_hlp[rb][b*512 + k];
                float mix = (k < 64) ? g_hs[rb][b*64 + k] : g_hnew[rb][b*512 + k];
                val = r0s[b]*hl + r1s[b]*mix;
            }
            As[b*132 + kk] = val;
            if (k >= dlo && k < dhi) g_hnew[w][b*512 + k] = val;  // publish H(t) slice
        }
        for (int i = 0; i < 16; i++){
            int e = i*256 + tid;
            int kk = e >> 5, n = e & 31;
            Bs[kk*40 + n] = g_Whh_u[(size_t)(kc*128 + kk)*2048 + ct*32 + n];
        }
        __syncthreads();
        #pragma unroll
        for (int ks = 0; ks < 16; ks++){
            int kk = ks*8;
            unsigned a0 = f2t(As[(wv*16 + fr    )*132 + kk + fc    ]);
            unsigned a1 = f2t(As[(wv*16 + fr + 8)*132 + kk + fc    ]);
            unsigned a2 = f2t(As[(wv*16 + fr    )*132 + kk + fc + 4]);
            unsigned a3 = f2t(As[(wv*16 + fr + 8)*132 + kk + fc + 4]);
            #pragma unroll
            for (int nf = 0; nf < 4; nf++){
                unsigned b0 = Bs[(kk + fc    )*40 + nf*8 + fr];
                unsigned b1 = Bs[(kk + fc + 4)*40 + nf*8 + fr];
                mma8(acc[nf], a0, a1, a2, a3, b0, b1);
            }
        }
        __syncthreads();
    }

    // epilogue: gates -> smem, then LSTM cell per (b, dim)
    float* gw_ = gsc + wv*16*33;
    size_t xbase = (size_t)(t*128)*2048 + ct*32;
    #pragma unroll
    for (int nf = 0; nf < 4; nf++){
        int rl = wv*16 + fr;
        int cl = nf*8 + fc*2;
        gw_[(fr    )*33 + cl]   = acc[nf][0] + g_Xl[xbase + (size_t)rl*2048 + cl];
        gw_[(fr    )*33 + cl+1] = acc[nf][1] + g_Xl[xbase + (size_t)rl*2048 + cl + 1];
        gw_[(fr + 8)*33 + cl]   = acc[nf][2] + g_Xl[xbase + (size_t)(rl+8)*2048 + cl];
        gw_[(fr + 8)*33 + cl+1] = acc[nf][3] + g_Xl[xbase + (size_t)(rl+8)*2048 + cl + 1];
    }
    __syncwarp();
    #pragma unroll
    for (int i = 0; i < 4; i++){
        int idx = lane + 32*i;          // 0..127 cells per warp
        int bl = idx >> 3, dloc = idx & 7;
        int b = wv*16 + bl;
        int dg = dlo + dloc;
        float gi = gw_[bl*33 + dloc*4 + 0];
        float gf = gw_[bl*33 + dloc*4 + 1];
        float gg = gw_[bl*33 + dloc*4 + 2];
        float go = gw_[bl*33 + dloc*4 + 3];
        float cp;
        if (t == 0) cp = 0.f;
        else {
            float cpl = g_clp[b*512 + dg];
            cp = (dg < 64) ? (r0s[b]*cpl + r1s[b]*g_cs[rb][b*64 + dg]) : cpl;
        }
        float c2 = sigf(gf)*cp + sigf(gi)*tanhf(gg);
        float h2 = sigf(go)*tanhf(c2);
        g_clp[b*512 + dg] = c2;
        g_hlp[w][b*512 + dg] = h2;
        float p0 = h2*wg[512 + dg]        + c2*wg[1024 + dg];
        float p1 = h2*wg[1536 + 512 + dg] + c2*wg[1536 + 1024 + dg];
        #pragma unroll
        for (int o = 4; o > 0; o >>= 1){
            p0 += __shfl_xor_sync(0xffffffffu, p0, o);
            p1 += __shfl_xor_sync(0xffffffffu, p1, o);
        }
        if ((lane & 7) == 0){
            g_ppart[w][(ct*128 + b)*2]     = p0;
            g_ppart[w][(ct*128 + b)*2 + 1] = p1;
        }
    }
}

// ------------------------- 6) classifier epilogue --------------------------
__global__ void k_out(const float* __restrict__ gum, const float* __restrict__ wcls,
                      const float* __restrict__ bcls, float* __restrict__ out){
    __shared__ float y[2];
    __shared__ float red0[128], red1[128];
    int b = blockIdx.x, tid = threadIdx.x;
    if (tid < 2){
        float yy = g_pe[(99*128 + b)*2 + tid];
        for (int j = 0; j < 64; j++) yy += g_ppart[1][(j*128 + b)*2 + tid];
        float u = gum[(99*128 + b)*2 + tid];
        yy -= logf(-logf(u + EPSG) + EPSG);
        y[tid] = yy;
    }
    __syncthreads();
    float mx = fmaxf(y[0], y[1]);
    float e0 = __expf(y[0]-mx), e1 = __expf(y[1]-mx);
    float r0 = e0/(e0 + e1), r1 = 1.f - r0;
    float s0 = 0.f, s1 = 0.f;
    for (int d = tid; d < 512; d += 128){
        float hl  = g_hlp[1][b*512 + d];
        float mix = (d < 64) ? g_hs[1][b*64 + d] : g_hnew[1][b*512 + d];
        float h = fmaxf(r0*hl + r1*mix, 0.f);
        s0 += h*wcls[d];
        s1 += h*wcls[512 + d];
    }
    red0[tid] = s0; red1[tid] = s1;
    __syncthreads();
    for (int o = 64; o > 0; o >>= 1){
        if (tid < o){ red0[tid] += red0[tid+o]; red1[tid] += red1[tid+o]; }
        __syncthreads();
    }
    if (tid == 0){
        out[b*2]     = red0[0] + bcls[0];
        out[b*2 + 1] = red1[0] + bcls[1];
    }
}

// ------------------------- host --------------------------------------------
extern "C" void kernel_launch(void* const* d_in, const int* in_sizes, int n_in,
                              void* d_out, int out_size){
    const int*   x    = (const int*)  d_in[0];
    const float* gum  = (const float*)d_in[5];
    const float* emb  = (const float*)d_in[6];
    const float* wihl = (const float*)d_in[7];
    const float* whhl = (const float*)d_in[8];
    const float* bihl = (const float*)d_in[9];
    const float* bhhl = (const float*)d_in[10];
    const float* wihs = (const float*)d_in[11];
    const float* whhs = (const float*)d_in[12];
    const float* bihs = (const float*)d_in[13];
    const float* bhhs = (const float*)d_in[14];
    const float* wg   = (const float*)d_in[15];
    const float* bg   = (const float*)d_in[16];
    const float* wcls = (const float*)d_in[17];
    const float* bcls = (const float*)d_in[18];
    float* out = (float*)d_out;

    const int gemm_sm = (128*132 + 128*72)*4;                       // 104448
    const int step_sm = (128*132 + 128*40 + 256 + 8*16*33)*4;       // 105984
    cudaFuncSetAttribute(k_gemm, cudaFuncAttributeMaxDynamicSharedMemorySize, gemm_sm);
    cudaFuncSetAttribute(k_step, cudaFuncAttributeMaxDynamicSharedMemorySize, step_sm);

    k_embed<<<M_N, 128>>>(x, emb);
    k_repack<<<8713, 256>>>(wihl, whhl, bihl, bhhl, wihs, bihs, bhhs);
    dim3 g1(100, 32); k_gemm<<<g1, 256, gemm_sm>>>(0);
    dim3 g2(100, 4);  k_gemm<<<g2, 256, gemm_sm>>>(1);
    k_pe<<<100, 256>>>(wg, bg);
    for (int t = 0; t < 100; t++)
        k_step<<<72, 256, step_sm>>>(t, gum, wg, whhs);
    k_out<<<128, 128>>>(gum, wcls, bcls, out);
}

// round 6
// speedup vs baseline: 1.0045x; 1.0045x over previous
#include <cuda_runtime.h>
#include <math.h>

#define S_T 100
#define B_N 128
#define D_N 512
#define SM_N 64
#define M_N (S_T*B_N)
#define EPSG 1e-20f

// ------------------------- device scratch (no allocs allowed) -------------
__device__ float    g_e[M_N*D_N];          // summed embeddings [m][512], m=s*128+b
__device__ float    g_Xl[(size_t)M_N*2048];// e@Wih_l^T + biases, permuted cols (d*4+q)
__device__ float    g_Xs[M_N*256];         // e@Wih_s^T + biases, natural cols (q*64+d)
__device__ float    g_pe[M_N*2];           // e-part of gate logits + b_gate
__device__ unsigned g_Wih_u[D_N*2048];     // tf32-packed [k][d*4+q]
__device__ unsigned g_Whh_u[D_N*2048];     // tf32-packed [k][d*4+q]
__device__ unsigned g_Wihs_u[D_N*256];     // tf32-packed [k][q*64+d]
__device__ float    g_bias_l[2048];
__device__ float    g_bias_s[256];
__device__ float    g_hlp[2][B_N*D_N];     // h_l'(t), parity t&1
__device__ float    g_clp[B_N*D_N];        // c_l'(t), single buffer (owner-local RMW)
__device__ float    g_hnew[2][B_N*D_N];    // H(t) written at step t to buf t&1
__device__ float    g_hs[2][B_N*SM_N];     // small-LSTM h_s2(t)
__device__ float    g_cs[2][B_N*SM_N];
__device__ float    g_ppart[2][64*B_N*2];  // gate-logit partials per n-tile

// ------------------------- helpers ----------------------------------------
__device__ __forceinline__ unsigned f2t(float x){
    unsigned r; asm("cvt.rna.tf32.f32 %0, %1;" : "=r"(r) : "f"(x)); return r;
}
__device__ __forceinline__ void mma8(float* c, unsigned a0, unsigned a1, unsigned a2,
                                     unsigned a3, unsigned b0, unsigned b1){
    asm volatile(
      "mma.sync.aligned.m16n8k8.row.col.f32.tf32.tf32.f32 "
      "{%0,%1,%2,%3},{%4,%5,%6,%7},{%8,%9},{%0,%1,%2,%3};\n"
      : "+f"(c[0]), "+f"(c[1]), "+f"(c[2]), "+f"(c[3])
      : "r"(a0), "r"(a1), "r"(a2), "r"(a3), "r"(b0), "r"(b1));
}
__device__ __forceinline__ float sigf(float x){ return 1.f/(1.f+__expf(-x)); }

// ------------------------- 1) embedding gather-sum -------------------------
__global__ void k_embed(const int* __restrict__ x, const float* __restrict__ emb){
    int m = blockIdx.x;            // m = s*128 + b
    int s = m >> 7, b = m & 127;
    const int* codes = x + (b*S_T + s)*16;
    int d = threadIdx.x * 4;
    float4 acc = make_float4(0.f,0.f,0.f,0.f);
    #pragma unroll
    for (int n = 0; n < 16; n++){
        int c = codes[n];
        float4 v = *reinterpret_cast<const float4*>(emb + (size_t)c*D_N + d);
        acc.x += v.x; acc.y += v.y; acc.z += v.z; acc.w += v.w;
    }
    *reinterpret_cast<float4*>(g_e + (size_t)m*D_N + d) = acc;
}

// ------------------------- 2) weight repack (tf32 + permute) ---------------
__global__ void k_repack(const float* __restrict__ wihl, const float* __restrict__ whhl,
                         const float* __restrict__ bihl, const float* __restrict__ bhhl,
                         const float* __restrict__ wihs, const float* __restrict__ bihs,
                         const float* __restrict__ bhhs){
    long idx = (long)blockIdx.x*256 + threadIdx.x;
    if (blockIdx.x < 4096){                      // Whh: out[k*2048 + d*4+q]
        int k = (int)(idx >> 11), n = (int)(idx & 2047);
        int q = n & 3, dd = n >> 2;
        g_Whh_u[idx] = f2t(whhl[(size_t)(q*512+dd)*512 + k]);
    } else if (blockIdx.x < 8192){               // Wih
        long i = idx - 2048L*512;
        int k = (int)(i >> 11), n = (int)(i & 2047);
        int q = n & 3, dd = n >> 2;
        g_Wih_u[i] = f2t(wihl[(size_t)(q*512+dd)*512 + k]);
    } else if (blockIdx.x < 8704){               // Wihs: out[k*256 + n], n natural
        long i = idx - 2L*2048*512;
        int k = (int)(i >> 8), n = (int)(i & 255);
        g_Wihs_u[i] = f2t(wihs[(size_t)n*512 + k]);
    } else if (blockIdx.x < 8712){               // bias_l (permuted)
        int n = (int)(idx - (2L*2048*512 + 512L*256));
        int q = n & 3, dd = n >> 2;
        g_bias_l[n] = bihl[q*512+dd] + bhhl[q*512+dd];
    } else {
        int n = threadIdx.x;
        g_bias_s[n] = bihs[n] + bhhs[n];
    }
}

// ------------------------- 3) input GEMMs (tf32 mma) -----------------------
// C[M,N] = g_e[M,512] @ Bp[512,N] + bias[N].  CTA tile 128x64, K chunks of 128.
__global__ void k_gemm(int mode){
    extern __shared__ float sm[];
    float*    As = sm;                                 // [128][132]
    unsigned* Bs = (unsigned*)(sm + 128*132);          // [128][72]
    const unsigned* Bp = mode ? g_Wihs_u : g_Wih_u;
    const float* bias  = mode ? g_bias_s : g_bias_l;
    float* C           = mode ? g_Xs    : g_Xl;
    const int N        = mode ? 256     : 2048;
    int bm = blockIdx.x, bn = blockIdx.y;
    int tid = threadIdx.x, wv = tid >> 5, lane = tid & 31;
    int fr = lane >> 2, fc = lane & 3;
    float acc[8][4];
    #pragma unroll
    for (int i = 0; i < 8; i++){
        #pragma unroll
        for (int j = 0; j < 4; j++) acc[i][j] = 0.f;
    }
    for (int kc = 0; kc < 4; kc++){
        for (int i = 0; i < 64; i++){
            int e = i*256 + tid;
            int r = e >> 7, c = e & 127;
            As[r*132 + c] = g_e[(size_t)(bm*128 + r)*512 + kc*128 + c];
        }
        for (int i = 0; i < 32; i++){
            int e = i*256 + tid;
            int k = e >> 6, n = e & 63;
            Bs[k*72 + n] = Bp[(size_t)(kc*128 + k)*N + bn*64 + n];
        }
        __syncthreads();
        #pragma unroll
        for (int ks = 0; ks < 16; ks++){
            int kk = ks*8;
            unsigned a0 = f2t(As[(wv*16 + fr    )*132 + kk + fc    ]);
            unsigned a1 = f2t(As[(wv*16 + fr + 8)*132 + kk + fc    ]);
            unsigned a2 = f2t(As[(wv*16 + fr    )*132 + kk + fc + 4]);
            unsigned a3 = f2t(As[(wv*16 + fr + 8)*132 + kk + fc + 4]);
            #pragma unroll
            for (int nf = 0; nf < 8; nf++){
                unsigned b0 = Bs[(kk + fc    )*72 + nf*8 + fr];
                unsigned b1 = Bs[(kk + fc + 4)*72 + nf*8 + fr];
                mma8(acc[nf], a0, a1, a2, a3, b0, b1);
            }
        }
        __syncthreads();
    }
    #pragma unroll
    for (int nf = 0; nf < 8; nf++){
        int row = bm*128 + wv*16 + fr;
        int col = bn*64 + nf*8 + fc*2;
        float b0 = bias[col], b1 = bias[col+1];
        C[(size_t)row*N + col]       = acc[nf][0] + b0;
        C[(size_t)row*N + col + 1]   = acc[nf][1] + b1;
        C[(size_t)(row+8)*N + col]   = acc[nf][2] + b0;
        C[(size_t)(row+8)*N + col+1] = acc[nf][3] + b1;
    }
}

// ------------------------- 4) e-part of gate logits ------------------------
__global__ void k_pe(const float* __restrict__ wg, const float* __restrict__ bg){
    int gw = blockIdx.x*8 + (threadIdx.x >> 5);
    int lane = threadIdx.x & 31;
    int stride = gridDim.x*8;
    for (int m = gw; m < M_N; m += stride){
        float s0 = 0.f, s1 = 0.f;
        for (int k = lane; k < 512; k += 32){
            float ev = g_e[(size_t)m*512 + k];
            s0 += ev*wg[k];
            s1 += ev*wg[1536 + k];
        }
        #pragma unroll
        for (int o = 16; o > 0; o >>= 1){
            s0 += __shfl_xor_sync(0xffffffffu, s0, o);
            s1 += __shfl_xor_sync(0xffffffffu, s1, o);
        }
        if (lane == 0){ g_pe[m*2] = s0 + bg[0]; g_pe[m*2+1] = s1 + bg[1]; }
    }
}

// ------------------------- 5) per-step kernel ------------------------------
// blocks 0..63: recurrent GEMM (32 permuted cols = 8 hidden dims each) + cell
// blocks 64..71: small LSTM (16 batch rows each)
__global__ void k_step(int t, const float* __restrict__ gum, const float* __restrict__ wg,
                       const float* __restrict__ whs_g){
    extern __shared__ float sm[];
    int tid = threadIdx.x;
    int w = t & 1, rb = 1 - w;

    if (blockIdx.x >= 64){
        // ---- small LSTM ----
        float* whs = sm;                // [256][65]
        float* hss = sm + 256*65;       // [16][64]
        float* css = hss + 16*64;       // [16][64]
        int cta = blockIdx.x - 64;
        int b0 = cta*16;
        for (int i = tid; i < 256*64; i += 256)
            whs[(i>>6)*65 + (i&63)] = whs_g[i];
        for (int i = tid; i < 16*64; i += 256){
            int bl = i >> 6, k = i & 63;
            hss[i] = t ? g_hs[rb][(b0+bl)*64 + k] : 0.f;
            css[i] = t ? g_cs[rb][(b0+bl)*64 + k] : 0.f;
        }
        __syncthreads();
        int d = tid & 63, blb = tid >> 6;
        for (int i = 0; i < 4; i++){
            int bl = blb + i*4;
            int b = b0 + bl;
            size_t xb = (size_t)(t*128 + b)*256;
            float gi = g_Xs[xb + d];
            float gf = g_Xs[xb + 64 + d];
            float gg = g_Xs[xb + 128 + d];
            float go = g_Xs[xb + 192 + d];
            for (int k = 0; k < 64; k++){
                float h = hss[bl*64 + k];
                gi += h*whs[(d      )*65 + k];
                gf += h*whs[(64  + d)*65 + k];
                gg += h*whs[(128 + d)*65 + k];
                go += h*whs[(192 + d)*65 + k];
            }
            float cp = css[bl*64 + d];
            float c2 = sigf(gf)*cp + sigf(gi)*tanhf(gg);
            float h2 = sigf(go)*tanhf(c2);
            g_hs[w][b*64 + d] = h2;
            g_cs[w][b*64 + d] = c2;
        }
        return;
    }

    // ---- recurrent GEMM CTA ----
    float*    As  = sm;                                 // [128][132]
    unsigned* Bs  = (unsigned*)(sm + 128*132);          // [128][40]
    float*    r0s = sm + 128*132 + 128*40;
    float*    r1s = r0s + 128;
    float*    gsc = r1s + 128;                          // 8 x [16][33]
    int ct = blockIdx.x;
    int wv = tid >> 5, lane = tid & 31;
    int fr = lane >> 2, fc = lane & 3;
    int dlo = ct*8, dhi = dlo + 8;

    if (t > 0 && tid < 128){
        int b = tid;
        float y0 = g_pe[((t-1)*128 + b)*2];
        float y1 = g_pe[((t-1)*128 + b)*2 + 1];
        for (int j = 0; j < 64; j++){
            y0 += g_ppart[rb][(j*128 + b)*2];
            y1 += g_ppart[rb][(j*128 + b)*2 + 1];
        }
        float u0 = gum[((t-1)*128 + b)*2];
        float u1 = gum[((t-1)*128 + b)*2 + 1];
        y0 -= logf(-logf(u0 + EPSG) + EPSG);
        y1 -= logf(-logf(u1 + EPSG) + EPSG);
        float mx = fmaxf(y0, y1);
        float e0 = __expf(y0 - mx), e1 = __expf(y1 - mx);
        float r0 = e0/(e0 + e1);
        r0s[b] = r0; r1s[b] = 1.f - r0;
    }
    __syncthreads();

    float acc[4][4];
    #pragma unroll
    for (int i = 0; i < 4; i++){
        #pragma unroll
        for (int j = 0; j < 4; j++) acc[i][j] = 0.f;
    }

    for (int kc = 0; kc < 4; kc++){
        // build A chunk = H(t)[:, kc*128 : kc*128+128] in fp32
        for (int i = 0; i < 64; i++){
            int e = i*256 + tid;
            int b = e >> 7, kk = e & 127;
            int k = kc*128 + kk;
            float val;
            if (t == 0) val = 0.f;
            else {
                float hl  = g_hlp[rb][b*512 + k];
                float mix = (k < 64) ? g_hs[rb][b*64 + k] : g_hnew[rb][b*512 + k];
                val = r0s[b]*hl + r1s[b]*mix;
            }
            As[b*132 + kk] = val;
            if (k >= dlo && k < dhi) g_hnew[w][b*512 + k] = val;  // publish H(t) slice
        }
        for (int i = 0; i < 16; i++){
            int e = i*256 + tid;
            int kk = e >> 5, n = e & 31;
            Bs[kk*40 + n] = g_Whh_u[(size_t)(kc*128 + kk)*2048 + ct*32 + n];
        }
        __syncthreads();
        #pragma unroll
        for (int ks = 0; ks < 16; ks++){
            int kk = ks*8;
            unsigned a0 = f2t(As[(wv*16 + fr    )*132 + kk + fc    ]);
            unsigned a1 = f2t(As[(wv*16 + fr + 8)*132 + kk + fc    ]);
            unsigned a2 = f2t(As[(wv*16 + fr    )*132 + kk + fc + 4]);
            unsigned a3 = f2t(As[(wv*16 + fr + 8)*132 + kk + fc + 4]);
            #pragma unroll
            for (int nf = 0; nf < 4; nf++){
                unsigned b0 = Bs[(kk + fc    )*40 + nf*8 + fr];
                unsigned b1 = Bs[(kk + fc + 4)*40 + nf*8 + fr];
                mma8(acc[nf], a0, a1, a2, a3, b0, b1);
            }
        }
        __syncthreads();
    }

    // epilogue: gates -> smem, then LSTM cell per (b, dim)
    float* gw_ = gsc + wv*16*33;
    size_t xbase = (size_t)(t*128)*2048 + ct*32;
    #pragma unroll
    for (int nf = 0; nf < 4; nf++){
        int rl = wv*16 + fr;
        int cl = nf*8 + fc*2;
        gw_[(fr    )*33 + cl]   = acc[nf][0] + g_Xl[xbase + (size_t)rl*2048 + cl];
        gw_[(fr    )*33 + cl+1] = acc[nf][1] + g_Xl[xbase + (size_t)rl*2048 + cl + 1];
        gw_[(fr + 8)*33 + cl]   = acc[nf][2] + g_Xl[xbase + (size_t)(rl+8)*2048 + cl];
        gw_[(fr + 8)*33 + cl+1] = acc[nf][3] + g_Xl[xbase + (size_t)(rl+8)*2048 + cl + 1];
    }
    __syncwarp();
    #pragma unroll
    for (int i = 0; i < 4; i++){
        int idx = lane + 32*i;          // 0..127 cells per warp
        int bl = idx >> 3, dloc = idx & 7;
        int b = wv*16 + bl;
        int dg = dlo + dloc;
        float gi = gw_[bl*33 + dloc*4 + 0];
        float gf = gw_[bl*33 + dloc*4 + 1];
        float gg = gw_[bl*33 + dloc*4 + 2];
        float go = gw_[bl*33 + dloc*4 + 3];
        float cp;
        if (t == 0) cp = 0.f;
        else {
            float cpl = g_clp[b*512 + dg];
            cp = (dg < 64) ? (r0s[b]*cpl + r1s[b]*g_cs[rb][b*64 + dg]) : cpl;
        }
        float c2 = sigf(gf)*cp + sigf(gi)*tanhf(gg);
        float h2 = sigf(go)*tanhf(c2);
        g_clp[b*512 + dg] = c2;
        g_hlp[w][b*512 + dg] = h2;
        float p0 = h2*wg[512 + dg]        + c2*wg[1024 + dg];
        float p1 = h2*wg[1536 + 512 + dg] + c2*wg[1536 + 1024 + dg];
        #pragma unroll
        for (int o = 4; o > 0; o >>= 1){
            p0 += __shfl_xor_sync(0xffffffffu, p0, o);
            p1 += __shfl_xor_sync(0xffffffffu, p1, o);
        }
        if ((lane & 7) == 0){
            g_ppart[w][(ct*128 + b)*2]     = p0;
            g_ppart[w][(ct*128 + b)*2 + 1] = p1;
        }
    }
}

// ------------------------- 6) classifier epilogue --------------------------
__global__ void k_out(const float* __restrict__ gum, const float* __restrict__ wcls,
                      const float* __restrict__ bcls, float* __restrict__ out){
    __shared__ float y[2];
    __shared__ float red0[128], red1[128];
    int b = blockIdx.x, tid = threadIdx.x;
    if (tid < 2){
        float yy = g_pe[(99*128 + b)*2 + tid];
        for (int j = 0; j < 64; j++) yy += g_ppart[1][(j*128 + b)*2 + tid];
        float u = gum[(99*128 + b)*2 + tid];
        yy -= logf(-logf(u + EPSG) + EPSG);
        y[tid] = yy;
    }
    __syncthreads();
    float mx = fmaxf(y[0], y[1]);
    float e0 = __expf(y[0]-mx), e1 = __expf(y[1]-mx);
    float r0 = e0/(e0 + e1), r1 = 1.f - r0;
    float s0 = 0.f, s1 = 0.f;
    for (int d = tid; d < 512; d += 128){
        float hl  = g_hlp[1][b*512 + d];
        float mix = (d < 64) ? g_hs[1][b*64 + d] : g_hnew[1][b*512 + d];
        float h = fmaxf(r0*hl + r1*mix, 0.f);
        s0 += h*wcls[d];
        s1 += h*wcls[512 + d];
    }
    red0[tid] = s0; red1[tid] = s1;
    __syncthreads();
    for (int o = 64; o > 0; o >>= 1){
        if (tid < o){ red0[tid] += red0[tid+o]; red1[tid] += red1[tid+o]; }
        __syncthreads();
    }
    if (tid == 0){
        out[b*2]     = red0[0] + bcls[0];
        out[b*2 + 1] = red1[0] + bcls[1];
    }
}

// ------------------------- host --------------------------------------------
extern "C" void kernel_launch(void* const* d_in, const int* in_sizes, int n_in,
                              void* d_out, int out_size){
    const int*   x    = (const int*)  d_in[0];
    const float* gum  = (const float*)d_in[5];
    const float* emb  = (const float*)d_in[6];
    const float* wihl = (const float*)d_in[7];
    const float* whhl = (const float*)d_in[8];
    const float* bihl = (const float*)d_in[9];
    const float* bhhl = (const float*)d_in[10];
    const float* wihs = (const float*)d_in[11];
    const float* whhs = (const float*)d_in[12];
    const float* bihs = (const float*)d_in[13];
    const float* bhhs = (const float*)d_in[14];
    const float* wg   = (const float*)d_in[15];
    const float* bg   = (const float*)d_in[16];
    const float* wcls = (const float*)d_in[17];
    const float* bcls = (const float*)d_in[18];
    float* out = (float*)d_out;

    const int gemm_sm = (128*132 + 128*72)*4;                       // 104448
    const int step_sm = (128*132 + 128*40 + 256 + 8*16*33)*4;       // 105984
    cudaFuncSetAttribute(k_gemm, cudaFuncAttributeMaxDynamicSharedMemorySize, gemm_sm);
    cudaFuncSetAttribute(k_step, cudaFuncAttributeMaxDynamicSharedMemorySize, step_sm);

    k_embed<<<M_N, 128>>>(x, emb);
    k_repack<<<8713, 256>>>(wihl, whhl, bihl, bhhl, wihs, bihs, bhhs);
    dim3 g1(100, 32); k_gemm<<<g1, 256, gemm_sm>>>(0);
    dim3 g2(100, 4);  k_gemm<<<g2, 256, gemm_sm>>>(1);
    k_pe<<<100, 256>>>(wg, bg);
    for (int t = 0; t < 100; t++)
        k_step<<<72, 256, step_sm>>>(t, gum, wg, whhs);
    k_out<<<128, 128>>>(gum, wcls, bcls, out);
}

// round 7
// speedup vs baseline: 3.4743x; 3.4586x over previous
#include <cuda_runtime.h>
#include <math.h>

#define S_T 100
#define B_N 128
#define D_N 512
#define SM_N 64
#define M_N (S_T*B_N)
#define EPSG 1e-20f
#define NC 72u

// ------------------------- device scratch (no allocs allowed) -------------
__device__ float    g_e[M_N*D_N];
__device__ float    g_Xl[(size_t)M_N*2048];   // permuted cols (d*4+q)
__device__ float    g_Xs[M_N*256];
__device__ float    g_pe[M_N*2];
__device__ unsigned g_Wih_u[D_N*2048];
__device__ unsigned g_Whh_u[D_N*2048];
__device__ unsigned g_Wihs_u[D_N*256];
__device__ float    g_bias_l[2048];
__device__ float    g_bias_s[256];
__device__ float    g_hlp[B_N*D_N];           // h_l'(t) (single buffer)
__device__ float    g_clp[B_N*D_N];           // c_l'(t) owner-thread RMW
__device__ float    g_H[2][B_N*D_N];          // H(t-1) built in phase1 of step t -> buf t&1
__device__ float    g_hs[2][B_N*SM_N];
__device__ float    g_cs[2][B_N*SM_N];
__device__ float    g_ppart[2][64*B_N*2];
__device__ unsigned g_bar;                    // grid barrier counter (reset by k_embed)

// ------------------------- helpers ----------------------------------------
__device__ __forceinline__ unsigned f2t(float x){
    unsigned r; asm("cvt.rna.tf32.f32 %0, %1;" : "=r"(r) : "f"(x)); return r;
}
__device__ __forceinline__ void mma8(float* c, unsigned a0, unsigned a1, unsigned a2,
                                     unsigned a3, unsigned b0, unsigned b1){
    asm volatile(
      "mma.sync.aligned.m16n8k8.row.col.f32.tf32.tf32.f32 "
      "{%0,%1,%2,%3},{%4,%5,%6,%7},{%8,%9},{%0,%1,%2,%3};\n"
      : "+f"(c[0]), "+f"(c[1]), "+f"(c[2]), "+f"(c[3])
      : "r"(a0), "r"(a1), "r"(a2), "r"(a3), "r"(b0), "r"(b1));
}
__device__ __forceinline__ float sigf(float x){ return 1.f/(1.f+__expf(-x)); }

__device__ __forceinline__ void gbar(unsigned target){
    __syncthreads();
    if (threadIdx.x == 0){
        __threadfence();
        atomicAdd(&g_bar, 1u);
        unsigned v;
        while (true){
            asm volatile("ld.acquire.gpu.b32 %0, [%1];" : "=r"(v) : "l"(&g_bar) : "memory");
            if (v >= target) break;
            __nanosleep(32);
        }
    }
    __syncthreads();
}

// ------------------------- 1) embedding gather-sum (+barrier reset) --------
__global__ void k_embed(const int* __restrict__ x, const float* __restrict__ emb){
    int m = blockIdx.x;            // m = s*128 + b
    if (m == 0 && threadIdx.x == 0) g_bar = 0u;
    int s = m >> 7, b = m & 127;
    const int* codes = x + (b*S_T + s)*16;
    int d = threadIdx.x * 4;
    float4 acc = make_float4(0.f,0.f,0.f,0.f);
    #pragma unroll
    for (int n = 0; n < 16; n++){
        int c = codes[n];
        float4 v = *reinterpret_cast<const float4*>(emb + (size_t)c*D_N + d);
        acc.x += v.x; acc.y += v.y; acc.z += v.z; acc.w += v.w;
    }
    *reinterpret_cast<float4*>(g_e + (size_t)m*D_N + d) = acc;
}

// ------------------------- 2) weight repack (tf32 + permute) ---------------
__global__ void k_repack(const float* __restrict__ wihl, const float* __restrict__ whhl,
                         const float* __restrict__ bihl, const float* __restrict__ bhhl,
                         const float* __restrict__ wihs, const float* __restrict__ bihs,
                         const float* __restrict__ bhhs){
    long idx = (long)blockIdx.x*256 + threadIdx.x;
    if (blockIdx.x < 4096){
        int k = (int)(idx >> 11), n = (int)(idx & 2047);
        int q = n & 3, dd = n >> 2;
        g_Whh_u[idx] = f2t(whhl[(size_t)(q*512+dd)*512 + k]);
    } else if (blockIdx.x < 8192){
        long i = idx - 2048L*512;
        int k = (int)(i >> 11), n = (int)(i & 2047);
        int q = n & 3, dd = n >> 2;
        g_Wih_u[i] = f2t(wihl[(size_t)(q*512+dd)*512 + k]);
    } else if (blockIdx.x < 8704){
        long i = idx - 2L*2048*512;
        int k = (int)(i >> 8), n = (int)(i & 255);
        g_Wihs_u[i] = f2t(wihs[(size_t)n*512 + k]);
    } else if (blockIdx.x < 8712){
        int n = (int)(idx - (2L*2048*512 + 512L*256));
        int q = n & 3, dd = n >> 2;
        g_bias_l[n] = bihl[q*512+dd] + bhhl[q*512+dd];
    } else {
        int n = threadIdx.x;
        g_bias_s[n] = bihs[n] + bhhs[n];
    }
}

// ------------------------- 3) input GEMMs (tf32 mma) -----------------------
__global__ void k_gemm(int mode){
    extern __shared__ float sm[];
    float*    As = sm;                                 // [128][132]
    unsigned* Bs = (unsigned*)(sm + 128*132);          // [128][72]
    const unsigned* Bp = mode ? g_Wihs_u : g_Wih_u;
    const float* bias  = mode ? g_bias_s : g_bias_l;
    float* C           = mode ? g_Xs    : g_Xl;
    const int N        = mode ? 256     : 2048;
    int bm = blockIdx.x, bn = blockIdx.y;
    int tid = threadIdx.x, wv = tid >> 5, lane = tid & 31;
    int fr = lane >> 2, fc = lane & 3;
    float acc[8][4];
    #pragma unroll
    for (int i = 0; i < 8; i++)
        #pragma unroll
        for (int j = 0; j < 4; j++) acc[i][j] = 0.f;
    for (int kc = 0; kc < 4; kc++){
        for (int i = 0; i < 64; i++){
            int e = i*256 + tid;
            int r = e >> 7, c = e & 127;
            As[r*132 + c] = g_e[(size_t)(bm*128 + r)*512 + kc*128 + c];
        }
        for (int i = 0; i < 32; i++){
            int e = i*256 + tid;
            int k = e >> 6, n = e & 63;
            Bs[k*72 + n] = Bp[(size_t)(kc*128 + k)*N + bn*64 + n];
        }
        __syncthreads();
        #pragma unroll
        for (int ks = 0; ks < 16; ks++){
            int kk = ks*8;
            unsigned a0 = f2t(As[(wv*16 + fr    )*132 + kk + fc    ]);
            unsigned a1 = f2t(As[(wv*16 + fr + 8)*132 + kk + fc    ]);
            unsigned a2 = f2t(As[(wv*16 + fr    )*132 + kk + fc + 4]);
            unsigned a3 = f2t(As[(wv*16 + fr + 8)*132 + kk + fc + 4]);
            #pragma unroll
            for (int nf = 0; nf < 8; nf++){
                unsigned b0 = Bs[(kk + fc    )*72 + nf*8 + fr];
                unsigned b1 = Bs[(kk + fc + 4)*72 + nf*8 + fr];
                mma8(acc[nf], a0, a1, a2, a3, b0, b1);
            }
        }
        __syncthreads();
    }
    #pragma unroll
    for (int nf = 0; nf < 8; nf++){
        int row = bm*128 + wv*16 + fr;
        int col = bn*64 + nf*8 + fc*2;
        float b0 = bias[col], b1 = bias[col+1];
        C[(size_t)row*N + col]       = acc[nf][0] + b0;
        C[(size_t)row*N + col + 1]   = acc[nf][1] + b1;
        C[(size_t)(row+8)*N + col]   = acc[nf][2] + b0;
        C[(size_t)(row+8)*N + col+1] = acc[nf][3] + b1;
    }
}

// ------------------------- 4) e-part of gate logits ------------------------
__global__ void k_pe(const float* __restrict__ wg, const float* __restrict__ bg){
    int gw = blockIdx.x*8 + (threadIdx.x >> 5);
    int lane = threadIdx.x & 31;
    int stride = gridDim.x*8;
    for (int m = gw; m < M_N; m += stride){
        float s0 = 0.f, s1 = 0.f;
        for (int k = lane; k < 512; k += 32){
            float ev = g_e[(size_t)m*512 + k];
            s0 += ev*wg[k];
            s1 += ev*wg[1536 + k];
        }
        #pragma unroll
        for (int o = 16; o > 0; o >>= 1){
            s0 += __shfl_xor_sync(0xffffffffu, s0, o);
            s1 += __shfl_xor_sync(0xffffffffu, s1, o);
        }
        if (lane == 0){ g_pe[m*2] = s0 + bg[0]; g_pe[m*2+1] = s1 + bg[1]; }
    }
}

// ------------------------- 5) persistent scan kernel -----------------------
// CTAs 0..63: recurrent GEMM, 32 permuted cols = 8 hidden dims each.
// CTAs 64..71: small LSTM, 16 batch rows each, state resident in smem.
// Two grid barriers per step:  A: ppart(t-1) ready -> phase1 computes r(t-1)
// and builds H(t-1) slice into g_H[t&1];  B: H ready -> phase2 GEMM+cell.
__global__ void __launch_bounds__(256, 1) k_seq(const float* __restrict__ gum,
                                                const float* __restrict__ wg,
                                                const float* __restrict__ whs_g){
    extern __shared__ float sm[];
    int tid = threadIdx.x;
    unsigned bt = 0;

    if (blockIdx.x >= 64){
        // ================= small LSTM CTA =================
        float* whs = sm;                 // [256][65]
        float* hss = sm + 256*65;        // [16][64]
        float* css = hss + 1024;         // [16][64]
        int b0 = (blockIdx.x - 64)*16;
        for (int i = tid; i < 256*64; i += 256)
            whs[(i>>6)*65 + (i&63)] = whs_g[i];
        for (int i = tid; i < 1024; i += 256){ hss[i] = 0.f; css[i] = 0.f; }
        __syncthreads();
        int d = tid & 63, blb = tid >> 6;
        for (int t = 0; t < S_T; t++){
            int w = t & 1;
            bt += NC; gbar(bt);                    // barrier A
            float h2v[4], c2v[4];
            #pragma unroll
            for (int i = 0; i < 4; i++){
                int bl = blb + i*4;
                int b = b0 + bl;
                size_t xb = (size_t)(t*128 + b)*256;
                float gi = g_Xs[xb + d];
                float gf = g_Xs[xb + 64 + d];
                float gg = g_Xs[xb + 128 + d];
                float go = g_Xs[xb + 192 + d];
                for (int k = 0; k < 64; k++){
                    float h = hss[bl*64 + k];
                    gi += h*whs[(d      )*65 + k];
                    gf += h*whs[(64  + d)*65 + k];
                    gg += h*whs[(128 + d)*65 + k];
                    go += h*whs[(192 + d)*65 + k];
                }
                float cp = css[bl*64 + d];
                float c2 = sigf(gf)*cp + sigf(gi)*tanhf(gg);
                float h2 = sigf(go)*tanhf(c2);
                h2v[i] = h2; c2v[i] = c2;
                g_hs[w][b*64 + d] = h2;
                g_cs[w][b*64 + d] = c2;
            }
            __syncthreads();
            #pragma unroll
            for (int i = 0; i < 4; i++){
                int bl = blb + i*4;
                hss[bl*64 + d] = h2v[i];
                css[bl*64 + d] = c2v[i];
            }
            bt += NC; gbar(bt);                    // barrier B
        }
        return;
    }

    // ================= recurrent GEMM CTA =================
    float*    As  = sm;                              // [128][132]
    unsigned* Bs  = (unsigned*)(sm + 128*132);       // [128][40]
    float*    r0s = sm + 128*132 + 128*40;           // [128]
    float*    r1s = r0s + 128;                       // [128]
    float*    gsc = r1s + 128;                       // 8 x [16][33]
    int ct = blockIdx.x;
    int wv = tid >> 5, lane = tid & 31;
    int fr = lane >> 2, fc = lane & 3;
    int dlo = ct*8;

    for (int t = 0; t < S_T; t++){
        int w = t & 1, rb = 1 - w;
        bt += NC; gbar(bt);                          // barrier A: ppart(t-1) ready

        // ---- phase 1: r(t-1) + H(t-1) slice ----
        if (t > 0){
            int b = tid >> 1, half = tid & 1;
            float y0 = 0.f, y1 = 0.f;
            for (int j = half*32; j < half*32 + 32; j++){
                float2 pp = __ldcg((const float2*)&g_ppart[rb][(j*128 + b)*2]);
                y0 += pp.x; y1 += pp.y;
            }
            y0 += __shfl_xor_sync(0xffffffffu, y0, 1);
            y1 += __shfl_xor_sync(0xffffffffu, y1, 1);
            if (!half){
                y0 += g_pe[((t-1)*128 + b)*2];
                y1 += g_pe[((t-1)*128 + b)*2 + 1];
                float u0 = gum[((t-1)*128 + b)*2];
                float u1 = gum[((t-1)*128 + b)*2 + 1];
                y0 -= logf(-logf(u0 + EPSG) + EPSG);
                y1 -= logf(-logf(u1 + EPSG) + EPSG);
                float mx = fmaxf(y0, y1);
                float e0 = __expf(y0 - mx), e1 = __expf(y1 - mx);
                float r0 = e0/(e0 + e1);
                r0s[b] = r0; r1s[b] = 1.f - r0;
            }
            __syncthreads();
            #pragma unroll
            for (int i = 0; i < 4; i++){
                int e = i*256 + tid;                 // 128b x 8d
                int b2 = e >> 3, dloc = e & 7;
                int dg = dlo + dloc;
                float hl  = __ldcg(&g_hlp[b2*512 + dg]);
                float mix = (dg < 64) ? __ldcg(&g_hs[rb][b2*64 + dg])
                                      : __ldcg(&g_H[rb][b2*512 + dg]);
                g_H[w][b2*512 + dg] = r0s[b2]*hl + r1s[b2]*mix;
            }
        } else {
            #pragma unroll
            for (int i = 0; i < 4; i++){
                int e = i*256 + tid;
                int b2 = e >> 3, dloc = e & 7;
                g_H[w][b2*512 + dlo + dloc] = 0.f;
            }
        }

        bt += NC; gbar(bt);                          // barrier B: H(t-1) ready

        // ---- phase 2: GEMM over H(t-1) + LSTM cell ----
        float acc[4][4];
        #pragma unroll
        for (int i = 0; i < 4; i++)
            #pragma unroll
            for (int j = 0; j < 4; j++) acc[i][j] = 0.f;

        if (t > 0){
            const float4* Hp = (const float4*)(&g_H[w][0]);
            for (int kc = 0; kc < 4; kc++){
                #pragma unroll
                for (int i = 0; i < 16; i++){
                    int e = i*256 + tid;             // 128 rows x 32 f4
                    int b2 = e >> 5, c4 = e & 31;
                    float4 v = __ldcg(Hp + (size_t)b2*128 + kc*32 + c4);
                    float* dst = &As[b2*132 + c4*4];
                    dst[0] = v.x; dst[1] = v.y; dst[2] = v.z; dst[3] = v.w;
                }
                #pragma unroll
                for (int i = 0; i < 16; i++){
                    int e = i*256 + tid;
                    int kk = e >> 5, n = e & 31;
                    Bs[kk*40 + n] = g_Whh_u[(size_t)(kc*128 + kk)*2048 + ct*32 + n];
                }
                __syncthreads();
                #pragma unroll
                for (int ks = 0; ks < 16; ks++){
                    int kk = ks*8;
                    unsigned a0 = f2t(As[(wv*16 + fr    )*132 + kk + fc    ]);
                    unsigned a1 = f2t(As[(wv*16 + fr + 8)*132 + kk + fc    ]);
                    unsigned a2 = f2t(As[(wv*16 + fr    )*132 + kk + fc + 4]);
                    unsigned a3 = f2t(As[(wv*16 + fr + 8)*132 + kk + fc + 4]);
                    #pragma unroll
                    for (int nf = 0; nf < 4; nf++){
                        unsigned b0 = Bs[(kk + fc    )*40 + nf*8 + fr];
                        unsigned b1 = Bs[(kk + fc + 4)*40 + nf*8 + fr];
                        mma8(acc[nf], a0, a1, a2, a3, b0, b1);
                    }
                }
                __syncthreads();
            }
        }

        // epilogue: gates -> smem, then cell per (b, dim)
        float* gw_ = gsc + wv*16*33;
        size_t xbase = (size_t)(t*128)*2048 + ct*32;
        #pragma unroll
        for (int nf = 0; nf < 4; nf++){
            int rl = wv*16 + fr;
            int cl = nf*8 + fc*2;
            gw_[(fr    )*33 + cl]   = acc[nf][0] + g_Xl[xbase + (size_t)rl*2048 + cl];
            gw_[(fr    )*33 + cl+1] = acc[nf][1] + g_Xl[xbase + (size_t)rl*2048 + cl + 1];
            gw_[(fr + 8)*33 + cl]   = acc[nf][2] + g_Xl[xbase + (size_t)(rl+8)*2048 + cl];
            gw_[(fr + 8)*33 + cl+1] = acc[nf][3] + g_Xl[xbase + (size_t)(rl+8)*2048 + cl + 1];
        }
        __syncwarp();
        #pragma unroll
        for (int i = 0; i < 4; i++){
            int idx = lane + 32*i;                   // 128 cells per warp
            int bl = idx >> 3, dloc = idx & 7;
            int b = wv*16 + bl;
            int dg = dlo + dloc;
            float gi = gw_[bl*33 + dloc*4 + 0];
            float gf = gw_[bl*33 + dloc*4 + 1];
            float gg = gw_[bl*33 + dloc*4 + 2];
            float go = gw_[bl*33 + dloc*4 + 3];
            float cp;
            if (t == 0) cp = 0.f;
            else {
                float cpl = g_clp[b*512 + dg];
                cp = (dg < 64) ? (r0s[b]*cpl + r1s[b]*__ldcg(&g_cs[rb][b*64 + dg])) : cpl;
            }
            float c2 = sigf(gf)*cp + sigf(gi)*tanhf(gg);
            float h2 = sigf(go)*tanhf(c2);
            g_clp[b*512 + dg] = c2;
            g_hlp[b*512 + dg] = h2;
            float p0 = h2*wg[512 + dg]        + c2*wg[1024 + dg];
            float p1 = h2*wg[1536 + 512 + dg] + c2*wg[1536 + 1024 + dg];
            #pragma unroll
            for (int o = 4; o > 0; o >>= 1){
                p0 += __shfl_xor_sync(0xffffffffu, p0, o);
                p1 += __shfl_xor_sync(0xffffffffu, p1, o);
            }
            if ((lane & 7) == 0){
                g_ppart[w][(ct*128 + b)*2]     = p0;
                g_ppart[w][(ct*128 + b)*2 + 1] = p1;
            }
        }
        __syncthreads();
    }
}

// ------------------------- 6) classifier epilogue --------------------------
__global__ void k_out(const float* __restrict__ gum, const float* __restrict__ wcls,
                      const float* __restrict__ bcls, float* __restrict__ out){
    __shared__ float y[2];
    __shared__ float red0[128], red1[128];
    int b = blockIdx.x, tid = threadIdx.x;
    if (tid < 2){
        float yy = g_pe[(99*128 + b)*2 + tid];
        for (int j = 0; j < 64; j++) yy += g_ppart[1][(j*128 + b)*2 + tid];
        float u = gum[(99*128 + b)*2 + tid];
        yy -= logf(-logf(u + EPSG) + EPSG);
        y[tid] = yy;
    }
    __syncthreads();
    float mx = fmaxf(y[0], y[1]);
    float e0 = __expf(y[0]-mx), e1 = __expf(y[1]-mx);
    float r0 = e0/(e0 + e1), r1 = 1.f - r0;
    float s0 = 0.f, s1 = 0.f;
    for (int d = tid; d < 512; d += 128){
        float hl  = g_hlp[b*512 + d];
        float mix = (d < 64) ? g_hs[1][b*64 + d] : g_H[1][b*512 + d];
        float h = fmaxf(r0*hl + r1*mix, 0.f);
        s0 += h*wcls[d];
        s1 += h*wcls[512 + d];
    }
    red0[tid] = s0; red1[tid] = s1;
    __syncthreads();
    for (int o = 64; o > 0; o >>= 1){
        if (tid < o){ red0[tid] += red0[tid+o]; red1[tid] += red1[tid+o]; }
        __syncthreads();
    }
    if (tid == 0){
        out[b*2]     = red0[0] + bcls[0];
        out[b*2 + 1] = red1[0] + bcls[1];
    }
}

// ------------------------- host --------------------------------------------
extern "C" void kernel_launch(void* const* d_in, const int* in_sizes, int n_in,
                              void* d_out, int out_size){
    const int*   x    = (const int*)  d_in[0];
    const float* gum  = (const float*)d_in[5];
    const float* emb  = (const float*)d_in[6];
    const float* wihl = (const float*)d_in[7];
    const float* whhl = (const float*)d_in[8];
    const float* bihl = (const float*)d_in[9];
    const float* bhhl = (const float*)d_in[10];
    const float* wihs = (const float*)d_in[11];
    const float* whhs = (const float*)d_in[12];
    const float* bihs = (const float*)d_in[13];
    const float* bhhs = (const float*)d_in[14];
    const float* wg   = (const float*)d_in[15];
    const float* bg   = (const float*)d_in[16];
    const float* wcls = (const float*)d_in[17];
    const float* bcls = (const float*)d_in[18];
    float* out = (float*)d_out;

    const int gemm_sm = (128*132 + 128*72)*4;                       // 104448
    const int seq_sm  = (128*132 + 128*40 + 256 + 8*16*33)*4;       // 105984
    cudaFuncSetAttribute(k_gemm, cudaFuncAttributeMaxDynamicSharedMemorySize, gemm_sm);
    cudaFuncSetAttribute(k_seq,  cudaFuncAttributeMaxDynamicSharedMemorySize, seq_sm);

    k_embed<<<M_N, 128>>>(x, emb);
    k_repack<<<8713, 256>>>(wihl, whhl, bihl, bhhl, wihs, bihs, bhhs);
    dim3 g1(100, 32); k_gemm<<<g1, 256, gemm_sm>>>(0);
    dim3 g2(100, 4);  k_gemm<<<g2, 256, gemm_sm>>>(1);
    k_pe<<<100, 256>>>(wg, bg);
    k_seq<<<72, 256, seq_sm>>>(gum, wg, whhs);
    k_out<<<128, 128>>>(gum, wcls, bcls, out);
}

// round 8
// speedup vs baseline: 3.7713x; 1.0855x over previous
#include <cuda_runtime.h>
#include <math.h>

#define S_T 100
#define B_N 128
#define D_N 512
#define SM_N 64
#define M_N (S_T*B_N)
#define EPSG 1e-20f
#define NC 136u
#define NG 128            // GEMM CTAs in k_seq

// ------------------------- device scratch (no allocs allowed) -------------
__device__ float    g_e[M_N*D_N];
__device__ unsigned g_eu[M_N*D_N];            // tf32-pre-rounded e
__device__ float    g_Xl[(size_t)M_N*2048];   // permuted cols (d*4+q)
__device__ float    g_Xs[M_N*256];
__device__ float    g_pe[M_N*2];
__device__ unsigned g_Wih_u[D_N*2048];
__device__ unsigned g_Whh_u[D_N*2048];
__device__ unsigned g_Wihs_u[D_N*256];
__device__ float    g_bias_l[2048];
__device__ float    g_bias_s[256];
__device__ float    g_hlp[B_N*D_N];           // h_l'(t)
__device__ float    g_clp[B_N*D_N];           // c_l'(t) owner RMW
__device__ float    g_H[2][B_N*D_N];          // H(t-1) fp32 (mix/classifier source)
__device__ unsigned g_Hu[2][B_N*D_N];         // H(t-1) tf32-pre-rounded (GEMM A)
__device__ float    g_hs[2][B_N*SM_N];
__device__ float    g_cs[2][B_N*SM_N];
__device__ float    g_ppart[2][NG*B_N*2];
__device__ unsigned g_bar;

// ------------------------- helpers ----------------------------------------
__device__ __forceinline__ unsigned f2t(float x){
    unsigned r; asm("cvt.rna.tf32.f32 %0, %1;" : "=r"(r) : "f"(x)); return r;
}
__device__ __forceinline__ void mma8(float* c, unsigned a0, unsigned a1, unsigned a2,
                                     unsigned a3, unsigned b0, unsigned b1){
    asm volatile(
      "mma.sync.aligned.m16n8k8.row.col.f32.tf32.tf32.f32 "
      "{%0,%1,%2,%3},{%4,%5,%6,%7},{%8,%9},{%0,%1,%2,%3};\n"
      : "+f"(c[0]), "+f"(c[1]), "+f"(c[2]), "+f"(c[3])
      : "r"(a0), "r"(a1), "r"(a2), "r"(a3), "r"(b0), "r"(b1));
}
__device__ __forceinline__ float sigf(float x){ return 1.f/(1.f+__expf(-x)); }

__device__ __forceinline__ void gbar(unsigned target){
    __syncthreads();
    if (threadIdx.x == 0){
        __threadfence();
        atomicAdd(&g_bar, 1u);
        unsigned v;
        while (true){
            asm volatile("ld.acquire.gpu.b32 %0, [%1];" : "=r"(v) : "l"(&g_bar) : "memory");
            if (v >= target) break;
            __nanosleep(32);
        }
    }
    __syncthreads();
}

// ------------------------- 1) embedding gather-sum (+barrier reset) --------
__global__ void k_embed(const int* __restrict__ x, const float* __restrict__ emb){
    int m = blockIdx.x;            // m = s*128 + b
    if (m == 0 && threadIdx.x == 0) g_bar = 0u;
    int s = m >> 7, b = m & 127;
    const int* codes = x + (b*S_T + s)*16;
    int d = threadIdx.x * 4;
    float4 acc = make_float4(0.f,0.f,0.f,0.f);
    #pragma unroll
    for (int n = 0; n < 16; n++){
        int c = codes[n];
        float4 v = *reinterpret_cast<const float4*>(emb + (size_t)c*D_N + d);
        acc.x += v.x; acc.y += v.y; acc.z += v.z; acc.w += v.w;
    }
    *reinterpret_cast<float4*>(g_e + (size_t)m*D_N + d) = acc;
    uint4 u; u.x = f2t(acc.x); u.y = f2t(acc.y); u.z = f2t(acc.z); u.w = f2t(acc.w);
    *reinterpret_cast<uint4*>(g_eu + (size_t)m*D_N + d) = u;
}

// ------------------------- 2) weight repack (tf32 + permute) ---------------
__global__ void k_repack(const float* __restrict__ wihl, const float* __restrict__ whhl,
                         const float* __restrict__ bihl, const float* __restrict__ bhhl,
                         const float* __restrict__ wihs, const float* __restrict__ bihs,
                         const float* __restrict__ bhhs){
    long idx = (long)blockIdx.x*256 + threadIdx.x;
    if (blockIdx.x < 4096){
        int k = (int)(idx >> 11), n = (int)(idx & 2047);
        int q = n & 3, dd = n >> 2;
        g_Whh_u[idx] = f2t(whhl[(size_t)(q*512+dd)*512 + k]);
    } else if (blockIdx.x < 8192){
        long i = idx - 2048L*512;
        int k = (int)(i >> 11), n = (int)(i & 2047);
        int q = n & 3, dd = n >> 2;
        g_Wih_u[i] = f2t(wihl[(size_t)(q*512+dd)*512 + k]);
    } else if (blockIdx.x < 8704){
        long i = idx - 2L*2048*512;
        int k = (int)(i >> 8), n = (int)(i & 255);
        g_Wihs_u[i] = f2t(wihs[(size_t)n*512 + k]);
    } else if (blockIdx.x < 8712){
        int n = (int)(idx - (2L*2048*512 + 512L*256));
        int q = n & 3, dd = n >> 2;
        g_bias_l[n] = bihl[q*512+dd] + bhhl[q*512+dd];
    } else {
        int n = threadIdx.x;
        g_bias_s[n] = bihs[n] + bhhs[n];
    }
}

// ------------------------- 3) input GEMMs (tf32 mma) -----------------------
__global__ void k_gemm(int mode){
    extern __shared__ float sm[];
    unsigned* As = (unsigned*)sm;                      // [128][132]
    unsigned* Bs = (unsigned*)(sm + 128*132);          // [128][72]
    const unsigned* Bp = mode ? g_Wihs_u : g_Wih_u;
    const float* bias  = mode ? g_bias_s : g_bias_l;
    float* C           = mode ? g_Xs    : g_Xl;
    const int N        = mode ? 256     : 2048;
    int bm = blockIdx.x, bn = blockIdx.y;
    int tid = threadIdx.x, wv = tid >> 5, lane = tid & 31;
    int fr = lane >> 2, fc = lane & 3;
    float acc[8][4];
    #pragma unroll
    for (int i = 0; i < 8; i++)
        #pragma unroll
        for (int j = 0; j < 4; j++) acc[i][j] = 0.f;
    for (int kc = 0; kc < 4; kc++){
        for (int i = 0; i < 64; i++){
            int e = i*256 + tid;
            int r = e >> 7, c = e & 127;
            As[r*132 + c] = g_eu[(size_t)(bm*128 + r)*512 + kc*128 + c];
        }
        for (int i = 0; i < 32; i++){
            int e = i*256 + tid;
            int k = e >> 6, n = e & 63;
            Bs[k*72 + n] = Bp[(size_t)(kc*128 + k)*N + bn*64 + n];
        }
        __syncthreads();
        #pragma unroll
        for (int ks = 0; ks < 16; ks++){
            int kk = ks*8;
            unsigned a0 = As[(wv*16 + fr    )*132 + kk + fc    ];
            unsigned a1 = As[(wv*16 + fr + 8)*132 + kk + fc    ];
            unsigned a2 = As[(wv*16 + fr    )*132 + kk + fc + 4];
            unsigned a3 = As[(wv*16 + fr + 8)*132 + kk + fc + 4];
            #pragma unroll
            for (int nf = 0; nf < 8; nf++){
                unsigned b0 = Bs[(kk + fc    )*72 + nf*8 + fr];
                unsigned b1 = Bs[(kk + fc + 4)*72 + nf*8 + fr];
                mma8(acc[nf], a0, a1, a2, a3, b0, b1);
            }
        }
        __syncthreads();
    }
    #pragma unroll
    for (int nf = 0; nf < 8; nf++){
        int row = bm*128 + wv*16 + fr;
        int col = bn*64 + nf*8 + fc*2;
        float b0 = bias[col], b1 = bias[col+1];
        C[(size_t)row*N + col]       = acc[nf][0] + b0;
        C[(size_t)row*N + col + 1]   = acc[nf][1] + b1;
        C[(size_t)(row+8)*N + col]   = acc[nf][2] + b0;
        C[(size_t)(row+8)*N + col+1] = acc[nf][3] + b1;
    }
}

// ------------------------- 4) e-part of gate logits ------------------------
__global__ void k_pe(const float* __restrict__ wg, const float* __restrict__ bg){
    int gw = blockIdx.x*8 + (threadIdx.x >> 5);
    int lane = threadIdx.x & 31;
    int stride = gridDim.x*8;
    for (int m = gw; m < M_N; m += stride){
        float s0 = 0.f, s1 = 0.f;
        for (int k = lane; k < 512; k += 32){
            float ev = g_e[(size_t)m*512 + k];
            s0 += ev*wg[k];
            s1 += ev*wg[1536 + k];
        }
        #pragma unroll
        for (int o = 16; o > 0; o >>= 1){
            s0 += __shfl_xor_sync(0xffffffffu, s0, o);
            s1 += __shfl_xor_sync(0xffffffffu, s1, o);
        }
        if (lane == 0){ g_pe[m*2] = s0 + bg[0]; g_pe[m*2+1] = s1 + bg[1]; }
    }
}

// ------------------------- 5) persistent scan kernel -----------------------
// CTAs 0..127: recurrent GEMM, 16 permuted cols = 4 hidden dims each.
// CTAs 128..135: small LSTM, 16 batch rows each, state resident in smem.
__global__ void __launch_bounds__(256, 1) k_seq(const float* __restrict__ gum,
                                                const float* __restrict__ wg,
                                                const float* __restrict__ whs_g){
    extern __shared__ float sm[];
    int tid = threadIdx.x;
    unsigned bt = 0;

    if (blockIdx.x >= NG){
        // ================= small LSTM CTA =================
        float* whs = sm;                 // [256][65]
        float* hss = sm + 256*65;        // [16][64]
        float* css = hss + 1024;         // [16][64]
        int b0 = (blockIdx.x - NG)*16;
        for (int i = tid; i < 256*64; i += 256)
            whs[(i>>6)*65 + (i&63)] = whs_g[i];
        for (int i = tid; i < 1024; i += 256){ hss[i] = 0.f; css[i] = 0.f; }
        __syncthreads();
        int d = tid & 63, blb = tid >> 6;
        for (int t = 0; t < S_T; t++){
            int w = t & 1;
            bt += NC; gbar(bt);                    // barrier A
            float h2v[4], c2v[4];
            #pragma unroll
            for (int i = 0; i < 4; i++){
                int bl = blb + i*4;
                int b = b0 + bl;
                size_t xb = (size_t)(t*128 + b)*256;
                float gi = g_Xs[xb + d];
                float gf = g_Xs[xb + 64 + d];
                float gg = g_Xs[xb + 128 + d];
                float go = g_Xs[xb + 192 + d];
                for (int k = 0; k < 64; k++){
                    float h = hss[bl*64 + k];
                    gi += h*whs[(d      )*65 + k];
                    gf += h*whs[(64  + d)*65 + k];
                    gg += h*whs[(128 + d)*65 + k];
                    go += h*whs[(192 + d)*65 + k];
                }
                float cp = css[bl*64 + d];
                float c2 = sigf(gf)*cp + sigf(gi)*tanhf(gg);
                float h2 = sigf(go)*tanhf(c2);
                h2v[i] = h2; c2v[i] = c2;
                g_hs[w][b*64 + d] = h2;
                g_cs[w][b*64 + d] = c2;
            }
            __syncthreads();
            #pragma unroll
            for (int i = 0; i < 4; i++){
                int bl = blb + i*4;
                hss[bl*64 + d] = h2v[i];
                css[bl*64 + d] = c2v[i];
            }
            bt += NC; gbar(bt);                    // barrier B
        }
        return;
    }

    // ================= recurrent GEMM CTA =================
    unsigned* As  = (unsigned*)sm;                   // [128][132]
    unsigned* Bs  = (unsigned*)(sm + 128*132);       // [128][24]
    float*    r0s = sm + 128*132 + 128*24;           // [128]
    float*    r1s = r0s + 128;                       // [128]
    float*    gsc = r1s + 128;                       // 8 x [16][17]
    int ct = blockIdx.x;
    int wv = tid >> 5, lane = tid & 31;
    int fr = lane >> 2, fc = lane & 3;
    int dlo = ct*4;

    for (int t = 0; t < S_T; t++){
        int w = t & 1, rb = 1 - w;
        bt += NC; gbar(bt);                          // barrier A: ppart(t-1) ready

        // ---- phase 1: r(t-1) + H(t-1) slice ----
        if (t > 0){
            int b = tid >> 1, half = tid & 1;
            float y0 = 0.f, y1 = 0.f;
            for (int j = half*64; j < half*64 + 64; j++){
                float2 pp = __ldcg((const float2*)&g_ppart[rb][(j*128 + b)*2]);
                y0 += pp.x; y1 += pp.y;
            }
            y0 += __shfl_xor_sync(0xffffffffu, y0, 1);
            y1 += __shfl_xor_sync(0xffffffffu, y1, 1);
            if (!half){
                y0 += g_pe[((t-1)*128 + b)*2];
                y1 += g_pe[((t-1)*128 + b)*2 + 1];
                float u0 = gum[((t-1)*128 + b)*2];
                float u1 = gum[((t-1)*128 + b)*2 + 1];
                y0 -= logf(-logf(u0 + EPSG) + EPSG);
                y1 -= logf(-logf(u1 + EPSG) + EPSG);
                float mx = fmaxf(y0, y1);
                float e0 = __expf(y0 - mx), e1 = __expf(y1 - mx);
                float r0 = e0/(e0 + e1);
                r0s[b] = r0; r1s[b] = 1.f - r0;
            }
            __syncthreads();
            #pragma unroll
            for (int i = 0; i < 2; i++){
                int e = i*256 + tid;                 // 128b x 4d
                int b2 = e >> 2, dloc = e & 3;
                int dg = dlo + dloc;
                float hl  = __ldcg(&g_hlp[b2*512 + dg]);
                float mix = (dg < 64) ? __ldcg(&g_hs[rb][b2*64 + dg])
                                      : __ldcg(&g_H[rb][b2*512 + dg]);
                float val = r0s[b2]*hl + r1s[b2]*mix;
                g_H[w][b2*512 + dg]  = val;
                g_Hu[w][b2*512 + dg] = f2t(val);
            }
        } else {
            #pragma unroll
            for (int i = 0; i < 2; i++){
                int e = i*256 + tid;
                int b2 = e >> 2, dloc = e & 3;
                g_H[w][b2*512 + dlo + dloc]  = 0.f;
                g_Hu[w][b2*512 + dlo + dloc] = 0u;
            }
        }

        bt += NC; gbar(bt);                          // barrier B: H(t-1) ready

        // ---- phase 2: GEMM over H(t-1) + LSTM cell ----
        float acc[2][4];
        #pragma unroll
        for (int i = 0; i < 2; i++)
            #pragma unroll
            for (int j = 0; j < 4; j++) acc[i][j] = 0.f;

        if (t > 0){
            const uint4* Hp = (const uint4*)(&g_Hu[w][0]);
            for (int kc = 0; kc < 4; kc++){
                #pragma unroll
                for (int i = 0; i < 16; i++){
                    int e = i*256 + tid;             // 128 rows x 32 u4
                    int b2 = e >> 5, c4 = e & 31;
                    uint4 v = __ldcg(Hp + (size_t)b2*128 + kc*32 + c4);
                    unsigned* dst = &As[b2*132 + c4*4];
                    dst[0] = v.x; dst[1] = v.y; dst[2] = v.z; dst[3] = v.w;
                }
                #pragma unroll
                for (int i = 0; i < 8; i++){
                    int e = i*256 + tid;
                    int kk = e >> 4, n = e & 15;
                    Bs[kk*24 + n] = g_Whh_u[(size_t)(kc*128 + kk)*2048 + ct*16 + n];
                }
                __syncthreads();
                #pragma unroll
                for (int ks = 0; ks < 16; ks++){
                    int kk = ks*8;
                    unsigned a0 = As[(wv*16 + fr    )*132 + kk + fc    ];
                    unsigned a1 = As[(wv*16 + fr + 8)*132 + kk + fc    ];
                    unsigned a2 = As[(wv*16 + fr    )*132 + kk + fc + 4];
                    unsigned a3 = As[(wv*16 + fr + 8)*132 + kk + fc + 4];
                    #pragma unroll
                    for (int nf = 0; nf < 2; nf++){
                        unsigned b0 = Bs[(kk + fc    )*24 + nf*8 + fr];
                        unsigned b1 = Bs[(kk + fc + 4)*24 + nf*8 + fr];
                        mma8(acc[nf], a0, a1, a2, a3, b0, b1);
                    }
                }
                __syncthreads();
            }
        }

        // epilogue: gates -> smem, then cell per (b, dim)
        float* gw_ = gsc + wv*16*17;
        size_t xbase = (size_t)(t*128)*2048 + ct*16;
        #pragma unroll
        for (int nf = 0; nf < 2; nf++){
            int rl = wv*16 + fr;
            int cl = nf*8 + fc*2;
            gw_[(fr    )*17 + cl]   = acc[nf][0] + g_Xl[xbase + (size_t)rl*2048 + cl];
            gw_[(fr    )*17 + cl+1] = acc[nf][1] + g_Xl[xbase + (size_t)rl*2048 + cl + 1];
            gw_[(fr + 8)*17 + cl]   = acc[nf][2] + g_Xl[xbase + (size_t)(rl+8)*2048 + cl];
            gw_[(fr + 8)*17 + cl+1] = acc[nf][3] + g_Xl[xbase + (size_t)(rl+8)*2048 + cl + 1];
        }
        __syncwarp();
        #pragma unroll
        for (int i = 0; i < 2; i++){
            int idx = lane + 32*i;                   // 64 cells per warp (16b x 4d)
            int bl = idx >> 2, dloc = idx & 3;
            int b = wv*16 + bl;
            int dg = dlo + dloc;
            float gi = gw_[bl*17 + dloc*4 + 0];
            float gf = gw_[bl*17 + dloc*4 + 1];
            float gg = gw_[bl*17 + dloc*4 + 2];
            float go = gw_[bl*17 + dloc*4 + 3];
            float cp;
            if (t == 0) cp = 0.f;
            else {
                float cpl = g_clp[b*512 + dg];
                cp = (dg < 64) ? (r0s[b]*cpl + r1s[b]*__ldcg(&g_cs[rb][b*64 + dg])) : cpl;
            }
            float c2 = sigf(gf)*cp + sigf(gi)*tanhf(gg);
            float h2 = sigf(go)*tanhf(c2);
            g_clp[b*512 + dg] = c2;
            g_hlp[b*512 + dg] = h2;
            float p0 = h2*wg[512 + dg]        + c2*wg[1024 + dg];
            float p1 = h2*wg[1536 + 512 + dg] + c2*wg[1536 + 1024 + dg];
            #pragma unroll
            for (int o = 2; o > 0; o >>= 1){
                p0 += __shfl_xor_sync(0xffffffffu, p0, o);
                p1 += __shfl_xor_sync(0xffffffffu, p1, o);
            }
            if ((lane & 3) == 0){
                g_ppart[w][(ct*128 + b)*2]     = p0;
                g_ppart[w][(ct*128 + b)*2 + 1] = p1;
            }
        }
        __syncthreads();
    }
}

// ------------------------- 6) classifier epilogue --------------------------
__global__ void k_out(const float* __restrict__ gum, const float* __restrict__ wcls,
                      const float* __restrict__ bcls, float* __restrict__ out){
    __shared__ float y[2];
    __shared__ float red0[128], red1[128];
    int b = blockIdx.x, tid = threadIdx.x;
    if (tid < 2){
        float yy = g_pe[(99*128 + b)*2 + tid];
        for (int j = 0; j < NG; j++) yy += g_ppart[1][(j*128 + b)*2 + tid];
        float u = gum[(99*128 + b)*2 + tid];
        yy -= logf(-logf(u + EPSG) + EPSG);
        y[tid] = yy;
    }
    __syncthreads();
    float mx = fmaxf(y[0], y[1]);
    float e0 = __expf(y[0]-mx), e1 = __expf(y[1]-mx);
    float r0 = e0/(e0 + e1), r1 = 1.f - r0;
    float s0 = 0.f, s1 = 0.f;
    for (int d = tid; d < 512; d += 128){
        float hl  = g_hlp[b*512 + d];
        float mix = (d < 64) ? g_hs[1][b*64 + d] : g_H[1][b*512 + d];
        float h = fmaxf(r0*hl + r1*mix, 0.f);
        s0 += h*wcls[d];
        s1 += h*wcls[512 + d];
    }
    red0[tid] = s0; red1[tid] = s1;
    __syncthreads();
    for (int o = 64; o > 0; o >>= 1){
        if (tid < o){ red0[tid] += red0[tid+o]; red1[tid] += red1[tid+o]; }
        __syncthreads();
    }
    if (tid == 0){
        out[b*2]     = red0[0] + bcls[0];
        out[b*2 + 1] = red1[0] + bcls[1];
    }
}

// ------------------------- host --------------------------------------------
extern "C" void kernel_launch(void* const* d_in, const int* in_sizes, int n_in,
                              void* d_out, int out_size){
    const int*   x    = (const int*)  d_in[0];
    const float* gum  = (const float*)d_in[5];
    const float* emb  = (const float*)d_in[6];
    const float* wihl = (const float*)d_in[7];
    const float* whhl = (const float*)d_in[8];
    const float* bihl = (const float*)d_in[9];
    const float* bhhl = (const float*)d_in[10];
    const float* wihs = (const float*)d_in[11];
    const float* whhs = (const float*)d_in[12];
    const float* bihs = (const float*)d_in[13];
    const float* bhhs = (const float*)d_in[14];
    const float* wg   = (const float*)d_in[15];
    const float* bg   = (const float*)d_in[16];
    const float* wcls = (const float*)d_in[17];
    const float* bcls = (const float*)d_in[18];
    float* out = (float*)d_out;

    const int gemm_sm = (128*132 + 128*72)*4;                       // 104448
    const int seq_sm  = (128*132 + 128*24 + 256 + 8*16*17)*4;       // 89600
    cudaFuncSetAttribute(k_gemm, cudaFuncAttributeMaxDynamicSharedMemorySize, gemm_sm);
    cudaFuncSetAttribute(k_seq,  cudaFuncAttributeMaxDynamicSharedMemorySize, seq_sm);

    k_embed<<<M_N, 128>>>(x, emb);
    k_repack<<<8713, 256>>>(wihl, whhl, bihl, bhhl, wihs, bihs, bhhs);
    dim3 g1(100, 32); k_gemm<<<g1, 256, gemm_sm>>>(0);
    dim3 g2(100, 4);  k_gemm<<<g2, 256, gemm_sm>>>(1);
    k_pe<<<100, 256>>>(wg, bg);
    k_seq<<<NG + 8, 256, seq_sm>>>(gum, wg, whhs);
    k_out<<<128, 128>>>(gum, wcls, bcls, out);
}

// round 10
// speedup vs baseline: 4.0182x; 1.0655x over previous
#include <cuda_runtime.h>
#include <math.h>

#define S_T 100
#define B_N 128
#define D_N 512
#define SM_N 64
#define M_N (S_T*B_N)
#define EPSG 1e-20f
#define NC 136u
#define NG 128            // GEMM CTAs in k_seq

// ------------------------- device scratch (no allocs allowed) -------------
__device__ float    g_e[M_N*D_N];
__device__ unsigned g_eu[M_N*D_N];            // tf32-pre-rounded e
__device__ float    g_Xl[(size_t)M_N*2048];   // permuted cols (d*4+q)
__device__ float    g_Xs[M_N*256];
__device__ float    g_pe[M_N*2];
__device__ unsigned g_Wih_u[D_N*2048];
__device__ unsigned g_Whh_u[D_N*2048];
__device__ unsigned g_Wihs_u[D_N*256];
__device__ float    g_bias_l[2048];
__device__ float    g_bias_s[256];
__device__ float    g_hlp[B_N*D_N];           // h_l'(t)
__device__ float    g_clp[B_N*D_N];           // c_l'(t) owner RMW
__device__ float    g_H[2][B_N*D_N];          // H(t-1) fp32 (mix/classifier source)
__device__ unsigned g_Hu[2][B_N*D_N];         // H(t-1) tf32-pre-rounded (GEMM A)
__device__ float    g_hs[2][B_N*SM_N];
__device__ float    g_cs[2][B_N*SM_N];
__device__ float    g_ppart[2][NG*B_N*2];
__device__ unsigned g_bar;

// ------------------------- helpers ----------------------------------------
__device__ __forceinline__ unsigned f2t(float x){
    unsigned r; asm("cvt.rna.tf32.f32 %0, %1;" : "=r"(r) : "f"(x)); return r;
}
__device__ __forceinline__ void mma8(float* c, unsigned a0, unsigned a1, unsigned a2,
                                     unsigned a3, unsigned b0, unsigned b1){
    asm volatile(
      "mma.sync.aligned.m16n8k8.row.col.f32.tf32.tf32.f32 "
      "{%0,%1,%2,%3},{%4,%5,%6,%7},{%8,%9},{%0,%1,%2,%3};\n"
      : "+f"(c[0]), "+f"(c[1]), "+f"(c[2]), "+f"(c[3])
      : "r"(a0), "r"(a1), "r"(a2), "r"(a3), "r"(b0), "r"(b1));
}
__device__ __forceinline__ float sigf(float x){ return 1.f/(1.f+__expf(-x)); }

__device__ __forceinline__ void cpa16(unsigned s, const void* g){
    asm volatile("cp.async.cg.shared.global [%0], [%1], 16;\n" :: "r"(s), "l"(g));
}
__device__ __forceinline__ void cpa_commit(){ asm volatile("cp.async.commit_group;\n" ::: "memory"); }
__device__ __forceinline__ void cpa_wait1(){ asm volatile("cp.async.wait_group 1;\n" ::: "memory"); }
__device__ __forceinline__ void cpa_wait0(){ asm volatile("cp.async.wait_group 0;\n" ::: "memory"); }

__device__ __forceinline__ void gbar(unsigned target){
    __syncthreads();
    if (threadIdx.x == 0){
        __threadfence();
        atomicAdd(&g_bar, 1u);
        unsigned v;
        while (true){
            asm volatile("ld.acquire.gpu.b32 %0, [%1];" : "=r"(v) : "l"(&g_bar) : "memory");
            if (v >= target) break;
            __nanosleep(32);
        }
    }
    __syncthreads();
}

// ------------------------- 1) embedding gather-sum (+barrier reset) --------
__global__ void k_embed(const int* __restrict__ x, const float* __restrict__ emb){
    int m = blockIdx.x;            // m = s*128 + b
    if (m == 0 && threadIdx.x == 0) g_bar = 0u;
    int s = m >> 7, b = m & 127;
    const int* codes = x + (b*S_T + s)*16;
    int d = threadIdx.x * 4;
    float4 acc = make_float4(0.f,0.f,0.f,0.f);
    #pragma unroll
    for (int n = 0; n < 16; n++){
        int c = codes[n];
        float4 v = *reinterpret_cast<const float4*>(emb + (size_t)c*D_N + d);
        acc.x += v.x; acc.y += v.y; acc.z += v.z; acc.w += v.w;
    }
    *reinterpret_cast<float4*>(g_e + (size_t)m*D_N + d) = acc;
    uint4 u; u.x = f2t(acc.x); u.y = f2t(acc.y); u.z = f2t(acc.z); u.w = f2t(acc.w);
    *reinterpret_cast<uint4*>(g_eu + (size_t)m*D_N + d) = u;
}

// ------------------------- 2) weight repack (tf32 + permute) ---------------
__global__ void k_repack(const float* __restrict__ wihl, const float* __restrict__ whhl,
                         const float* __restrict__ bihl, const float* __restrict__ bhhl,
                         const float* __restrict__ wihs, const float* __restrict__ bihs,
                         const float* __restrict__ bhhs){
    long idx = (long)blockIdx.x*256 + threadIdx.x;
    if (blockIdx.x < 4096){
        int k = (int)(idx >> 11), n = (int)(idx & 2047);
        int q = n & 3, dd = n >> 2;
        g_Whh_u[idx] = f2t(whhl[(size_t)(q*512+dd)*512 + k]);
    } else if (blockIdx.x < 8192){
        long i = idx - 2048L*512;
        int k = (int)(i >> 11), n = (int)(i & 2047);
        int q = n & 3, dd = n >> 2;
        g_Wih_u[i] = f2t(wihl[(size_t)(q*512+dd)*512 + k]);
    } else if (blockIdx.x < 8704){
        long i = idx - 2L*2048*512;
        int k = (int)(i >> 8), n = (int)(i & 255);
        g_Wihs_u[i] = f2t(wihs[(size_t)n*512 + k]);
    } else if (blockIdx.x < 8712){
        int n = (int)(idx - (2L*2048*512 + 512L*256));
        int q = n & 3, dd = n >> 2;
        g_bias_l[n] = bihl[q*512+dd] + bhhl[q*512+dd];
    } else {
        int n = threadIdx.x;
        g_bias_s[n] = bihs[n] + bhhs[n];
    }
}

// ------------------------- 3) input GEMMs (tf32 mma, occ=2) ----------------
__global__ void __launch_bounds__(256, 2) k_gemm(int mode){
    extern __shared__ float sm[];
    unsigned* As = (unsigned*)sm;                      // [128][132]
    unsigned* Bs = (unsigned*)(sm + 128*132);          // [128][72]
    const unsigned* Bp = mode ? g_Wihs_u : g_Wih_u;
    const float* bias  = mode ? g_bias_s : g_bias_l;
    float* C           = mode ? g_Xs    : g_Xl;
    const int N        = mode ? 256     : 2048;
    int bm = blockIdx.x, bn = blockIdx.y;
    int tid = threadIdx.x, wv = tid >> 5, lane = tid & 31;
    int fr = lane >> 2, fc = lane & 3;
    float acc[8][4];
    #pragma unroll
    for (int i = 0; i < 8; i++)
        #pragma unroll
        for (int j = 0; j < 4; j++) acc[i][j] = 0.f;
    for (int kc = 0; kc < 4; kc++){
        #pragma unroll
        for (int i = 0; i < 16; i++){
            int e = i*256 + tid;                       // 128 rows x 32 u4
            int r = e >> 5, c4 = e & 31;
            uint4 v = *reinterpret_cast<const uint4*>(
                &g_eu[(size_t)(bm*128 + r)*512 + kc*128 + c4*4]);
            unsigned* dst = &As[r*132 + c4*4];
            dst[0] = v.x; dst[1] = v.y; dst[2] = v.z; dst[3] = v.w;
        }
        #pragma unroll
        for (int i = 0; i < 8; i++){
            int e = i*256 + tid;                       // 128 rows x 16 u4
            int k = e >> 4, n4 = e & 15;
            uint4 v = *reinterpret_cast<const uint4*>(
                &Bp[(size_t)(kc*128 + k)*N + bn*64 + n4*4]);
            unsigned* dst = &Bs[k*72 + n4*4];
            dst[0] = v.x; dst[1] = v.y; dst[2] = v.z; dst[3] = v.w;
        }
        __syncthreads();
        #pragma unroll
        for (int ks = 0; ks < 16; ks++){
            int kk = ks*8;
            unsigned a0 = As[(wv*16 + fr    )*132 + kk + fc    ];
            unsigned a1 = As[(wv*16 + fr + 8)*132 + kk + fc    ];
            unsigned a2 = As[(wv*16 + fr    )*132 + kk + fc + 4];
            unsigned a3 = As[(wv*16 + fr + 8)*132 + kk + fc + 4];
            #pragma unroll
            for (int nf = 0; nf < 8; nf++){
                unsigned b0 = Bs[(kk + fc    )*72 + nf*8 + fr];
                unsigned b1 = Bs[(kk + fc + 4)*72 + nf*8 + fr];
                mma8(acc[nf], a0, a1, a2, a3, b0, b1);
            }
        }
        __syncthreads();
    }
    #pragma unroll
    for (int nf = 0; nf < 8; nf++){
        int row = bm*128 + wv*16 + fr;
        int col = bn*64 + nf*8 + fc*2;
        float b0 = bias[col], b1 = bias[col+1];
        C[(size_t)row*N + col]       = acc[nf][0] + b0;
        C[(size_t)row*N + col + 1]   = acc[nf][1] + b1;
        C[(size_t)(row+8)*N + col]   = acc[nf][2] + b0;
        C[(size_t)(row+8)*N + col+1] = acc[nf][3] + b1;
    }
}

// ------------------------- 4) e-part of gate logits ------------------------
__global__ void k_pe(const float* __restrict__ wg, const float* __restrict__ bg){
    int gw = blockIdx.x*8 + (threadIdx.x >> 5);
    int lane = threadIdx.x & 31;
    int stride = gridDim.x*8;
    for (int m = gw; m < M_N; m += stride){
        float s0 = 0.f, s1 = 0.f;
        for (int k = lane; k < 512; k += 32){
            float ev = g_e[(size_t)m*512 + k];
            s0 += ev*wg[k];
            s1 += ev*wg[1536 + k];
        }
        #pragma unroll
        for (int o = 16; o > 0; o >>= 1){
            s0 += __shfl_xor_sync(0xffffffffu, s0, o);
            s1 += __shfl_xor_sync(0xffffffffu, s1, o);
        }
        if (lane == 0){ g_pe[m*2] = s0 + bg[0]; g_pe[m*2+1] = s1 + bg[1]; }
    }
}

// ------------------------- 5) persistent scan kernel -----------------------
// CTAs 0..127: recurrent GEMM, 16 permuted cols = 4 hidden dims each.
// CTAs 128..135: small LSTM, 16 batch rows each, state resident in smem.
// Phase2 uses cp.async double-buffered A/B tiles to overlap L2 with mma.
__global__ void __launch_bounds__(256, 1) k_seq(const float* __restrict__ gum,
                                                const float* __restrict__ wg,
                                                const float* __restrict__ whs_g){
    extern __shared__ float sm[];
    int tid = threadIdx.x;
    unsigned bt = 0;

    if (blockIdx.x >= NG){
        // ================= small LSTM CTA =================
        float* whs = sm;                 // [256][65]
        float* hss = sm + 256*65;        // [16][64]
        float* css = hss + 1024;         // [16][64]
        int b0 = (blockIdx.x - NG)*16;
        for (int i = tid; i < 256*64; i += 256)
            whs[(i>>6)*65 + (i&63)] = whs_g[i];
        for (int i = tid; i < 1024; i += 256){ hss[i] = 0.f; css[i] = 0.f; }
        __syncthreads();
        int d = tid & 63, blb = tid >> 6;
        for (int t = 0; t < S_T; t++){
            int w = t & 1;
            bt += NC; gbar(bt);                    // barrier A
            float h2v[4], c2v[4];
            #pragma unroll
            for (int i = 0; i < 4; i++){
                int bl = blb + i*4;
                int b = b0 + bl;
                size_t xb = (size_t)(t*128 + b)*256;
                float gi = g_Xs[xb + d];
                float gf = g_Xs[xb + 64 + d];
                float gg = g_Xs[xb + 128 + d];
                float go = g_Xs[xb + 192 + d];
                for (int k = 0; k < 64; k++){
                    float h = hss[bl*64 + k];
                    gi += h*whs[(d      )*65 + k];
                    gf += h*whs[(64  + d)*65 + k];
                    gg += h*whs[(128 + d)*65 + k];
                    go += h*whs[(192 + d)*65 + k];
                }
                float cp = css[bl*64 + d];
                float c2 = sigf(gf)*cp + sigf(gi)*tanhf(gg);
                float h2 = sigf(go)*tanhf(c2);
                h2v[i] = h2; c2v[i] = c2;
                g_hs[w][b*64 + d] = h2;
                g_cs[w][b*64 + d] = c2;
            }
            __syncthreads();
            #pragma unroll
            for (int i = 0; i < 4; i++){
                int bl = blb + i*4;
                hss[bl*64 + d] = h2v[i];
                css[bl*64 + d] = c2v[i];
            }
            bt += NC; gbar(bt);                    // barrier B
        }
        return;
    }

    // ================= recurrent GEMM CTA =================
    const int ABUF = 128*132, BBUF = 128*24;
    unsigned* Asd = (unsigned*)sm;                   // 2 x [128][132]
    unsigned* Bsd = (unsigned*)(sm + 2*ABUF);        // 2 x [128][24]
    float*    r0s = sm + 2*ABUF + 2*BBUF;            // [128]
    float*    r1s = r0s + 128;                       // [128]
    float*    gsc = r1s + 128;                       // 8 x [16][17]
    unsigned  smem_u32 = (unsigned)__cvta_generic_to_shared(sm);
    int ct = blockIdx.x;
    int wv = tid >> 5, lane = tid & 31;
    int fr = lane >> 2, fc = lane & 3;
    int dlo = ct*4;

    for (int t = 0; t < S_T; t++){
        int w = t & 1, rb = 1 - w;

        // prefetch epilogue Xl operands (step-static) before the barrier spin
        float xl[8];
        {
            size_t xbase = (size_t)(t*128)*2048 + ct*16;
            #pragma unroll
            for (int nf = 0; nf < 2; nf++){
                int rl = wv*16 + fr;
                int cl = nf*8 + fc*2;
                xl[nf*4+0] = g_Xl[xbase + (size_t)rl*2048 + cl];
                xl[nf*4+1] = g_Xl[xbase + (size_t)rl*2048 + cl + 1];
                xl[nf*4+2] = g_Xl[xbase + (size_t)(rl+8)*2048 + cl];
                xl[nf*4+3] = g_Xl[xbase + (size_t)(rl+8)*2048 + cl + 1];
            }
        }

        bt += NC; gbar(bt);                          // barrier A: ppart(t-1) ready

        // ---- phase 1: r(t-1) + H(t-1) slice ----
        if (t > 0){
            int b = tid >> 1, half = tid & 1;
            float y0 = 0.f, y1 = 0.f;
            #pragma unroll 8
            for (int j = half*64; j < half*64 + 64; j++){
                float2 pp = __ldcg((const float2*)&g_ppart[rb][(j*128 + b)*2]);
                y0 += pp.x; y1 += pp.y;
            }
            y0 += __shfl_xor_sync(0xffffffffu, y0, 1);
            y1 += __shfl_xor_sync(0xffffffffu, y1, 1);
            if (!half){
                y0 += g_pe[((t-1)*128 + b)*2];
                y1 += g_pe[((t-1)*128 + b)*2 + 1];
                float u0 = gum[((t-1)*128 + b)*2];
                float u1 = gum[((t-1)*128 + b)*2 + 1];
                y0 -= logf(-logf(u0 + EPSG) + EPSG);
                y1 -= logf(-logf(u1 + EPSG) + EPSG);
                float mx = fmaxf(y0, y1);
                float e0 = __expf(y0 - mx), e1 = __expf(y1 - mx);
                float r0 = e0/(e0 + e1);
                r0s[b] = r0; r1s[b] = 1.f - r0;
            }
            __syncthreads();
            #pragma unroll
            for (int i = 0; i < 2; i++){
                int e = i*256 + tid;                 // 128b x 4d
                int b2 = e >> 2, dloc = e & 3;
                int dg = dlo + dloc;
                float hl  = __ldcg(&g_hlp[b2*512 + dg]);
                float mix = (dg < 64) ? __ldcg(&g_hs[rb][b2*64 + dg])
                                      : __ldcg(&g_H[rb][b2*512 + dg]);
                float val = r0s[b2]*hl + r1s[b2]*mix;
                g_H[w][b2*512 + dg]  = val;
                g_Hu[w][b2*512 + dg] = f2t(val);
            }
        } else {
            #pragma unroll
            for (int i = 0; i < 2; i++){
                int e = i*256 + tid;
                int b2 = e >> 2, dloc = e & 3;
                g_H[w][b2*512 + dlo + dloc]  = 0.f;
                g_Hu[w][b2*512 + dlo + dloc] = 0u;
            }
        }

        bt += NC; gbar(bt);                          // barrier B: H(t-1) ready

        // ---- phase 2: GEMM over H(t-1) (cp.async double-buffered) ----
        float acc[2][4];
        #pragma unroll
        for (int i = 0; i < 2; i++)
            #pragma unroll
            for (int j = 0; j < 4; j++) acc[i][j] = 0.f;

        if (t > 0){
            const unsigned* Hb = &g_Hu[w][0];
            const unsigned* Wb = g_Whh_u;
            // issue tile kc into buffer q
            auto issue = [&](int kc, int q){
                #pragma unroll
                for (int i = 0; i < 16; i++){
                    int e = i*256 + tid;             // 128 rows x 32 u4
                    int b2 = e >> 5, c4 = e & 31;
                    unsigned dst = smem_u32 + (unsigned)((q*ABUF + b2*132 + c4*4)*4);
                    cpa16(dst, Hb + (size_t)b2*512 + kc*128 + c4*4);
                }
                #pragma unroll
                for (int i = 0; i < 2; i++){
                    int e = i*256 + tid;             // 128 rows x 4 u4
                    int kk = e >> 2, n4 = e & 3;
                    unsigned dst = smem_u32 + (unsigned)((2*ABUF + q*BBUF + kk*24 + n4*4)*4);
                    cpa16(dst, Wb + (size_t)(kc*128 + kk)*2048 + ct*16 + n4*4);
                }
                cpa_commit();
            };
            issue(0, 0);
            #pragma unroll
            for (int kc = 0; kc < 4; kc++){
                int q = kc & 1;
                if (kc < 3){ issue(kc+1, 1-q); cpa_wait1(); }
                else       { cpa_wait0(); }
                __syncthreads();
                unsigned* Aq = Asd + q*ABUF;
                unsigned* Bq = Bsd + q*BBUF;
                #pragma unroll
                for (int ks = 0; ks < 16; ks++){
                    int kk = ks*8;
                    unsigned a0 = Aq[(wv*16 + fr    )*132 + kk + fc    ];
                    unsigned a1 = Aq[(wv*16 + fr + 8)*132 + kk + fc    ];
                    unsigned a2 = Aq[(wv*16 + fr    )*132 + kk + fc + 4];
                    unsigned a3 = Aq[(wv*16 + fr + 8)*132 + kk + fc + 4];
                    #pragma unroll
                    for (int nf = 0; nf < 2; nf++){
                        unsigned b0 = Bq[(kk + fc    )*24 + nf*8 + fr];
                        unsigned b1 = Bq[(kk + fc + 4)*24 + nf*8 + fr];
                        mma8(acc[nf], a0, a1, a2, a3, b0, b1);
                    }
                }
                __syncthreads();
            }
        }

        // epilogue: gates -> smem, then cell per (b, dim)
        float* gw_ = gsc + wv*16*17;
        #pragma unroll
        for (int nf = 0; nf < 2; nf++){
            int cl = nf*8 + fc*2;
            gw_[(fr    )*17 + cl]   = acc[nf][0] + xl[nf*4+0];
            gw_[(fr    )*17 + cl+1] = acc[nf][1] + xl[nf*4+1];
            gw_[(fr + 8)*17 + cl]   = acc[nf][2] + xl[nf*4+2];
            gw_[(fr + 8)*17 + cl+1] = acc[nf][3] + xl[nf*4+3];
        }
        __syncwarp();
        #pragma unroll
        for (int i = 0; i < 2; i++){
            int idx = lane + 32*i;                   // 64 cells per warp (16b x 4d)
            int bl = idx >> 2, dloc = idx & 3;
            int b = wv*16 + bl;
            int dg = dlo + dloc;
            float gi = gw_[bl*17 + dloc*4 + 0];
            float gf = gw_[bl*17 + dloc*4 + 1];
            float gg = gw_[bl*17 + dloc*4 + 2];
            float go = gw_[bl*17 + dloc*4 + 3];
            float cp;
            if (t == 0) cp = 0.f;
            else {
                float cpl = g_clp[b*512 + dg];
                cp = (dg < 64) ? (r0s[b]*cpl + r1s[b]*__ldcg(&g_cs[rb][b*64 + dg])) : cpl;
            }
            float c2 = sigf(gf)*cp + sigf(gi)*tanhf(gg);
            float h2 = sigf(go)*tanhf(c2);
            g_clp[b*512 + dg] = c2;
            g_hlp[b*512 + dg] = h2;
            float p0 = h2*wg[512 + dg]        + c2*wg[1024 + dg];
            float p1 = h2*wg[1536 + 512 + dg] + c2*wg[1536 + 1024 + dg];
            #pragma unroll
            for (int o = 2; o > 0; o >>= 1){
                p0 += __shfl_xor_sync(0xffffffffu, p0, o);
                p1 += __shfl_xor_sync(0xffffffffu, p1, o);
            }
            if ((lane & 3) == 0){
                g_ppart[w][(ct*128 + b)*2]     = p0;
                g_ppart[w][(ct*128 + b)*2 + 1] = p1;
            }
        }
        __syncthreads();
    }
}

// ------------------------- 6) classifier epilogue --------------------------
__global__ void k_out(const float* __restrict__ gum, const float* __restrict__ wcls,
                      const float* __restrict__ bcls, float* __restrict__ out){
    __shared__ float y[2];
    __shared__ float red0[128], red1[128];
    int b = blockIdx.x, tid = threadIdx.x;
    if (tid < 2){
        float yy = g_pe[(99*128 + b)*2 + tid];
        for (int j = 0; j < NG; j++) yy += g_ppart[1][(j*128 + b)*2 + tid];
        float u = gum[(99*128 + b)*2 + tid];
        yy -= logf(-logf(u + EPSG) + EPSG);
        y[tid] = yy;
    }
    __syncthreads();
    float mx = fmaxf(y[0], y[1]);
    float e0 = __expf(y[0]-mx), e1 = __expf(y[1]-mx);
    float r0 = e0/(e0 + e1), r1 = 1.f - r0;
    float s0 = 0.f, s1 = 0.f;
    for (int d = tid; d < 512; d += 128){
        float hl  = g_hlp[b*512 + d];
        float mix = (d < 64) ? g_hs[1][b*64 + d] : g_H[1][b*512 + d];
        float h = fmaxf(r0*hl + r1*mix, 0.f);
        s0 += h*wcls[d];
        s1 += h*wcls[512 + d];
    }
    red0[tid] = s0; red1[tid] = s1;
    __syncthreads();
    for (int o = 64; o > 0; o >>= 1){
        if (tid < o){ red0[tid] += red0[tid+o]; red1[tid] += red1[tid+o]; }
        __syncthreads();
    }
    if (tid == 0){
        out[b*2]     = red0[0] + bcls[0];
        out[b*2 + 1] = red1[0] + bcls[1];
    }
}

// ------------------------- host --------------------------------------------
extern "C" void kernel_launch(void* const* d_in, const int* in_sizes, int n_in,
                              void* d_out, int out_size){
    const int*   x    = (const int*)  d_in[0];
    const float* gum  = (const float*)d_in[5];
    const float* emb  = (const float*)d_in[6];
    const float* wihl = (const float*)d_in[7];
    const float* whhl = (const float*)d_in[8];
    const float* bihl = (const float*)d_in[9];
    const float* bhhl = (const float*)d_in[10];
    const float* wihs = (const float*)d_in[11];
    const float* whhs = (const float*)d_in[12];
    const float* bihs = (const float*)d_in[13];
    const float* bhhs = (const float*)d_in[14];
    const float* wg   = (const float*)d_in[15];
    const float* bg   = (const float*)d_in[16];
    const float* wcls = (const float*)d_in[17];
    const float* bcls = (const float*)d_in[18];
    float* out = (float*)d_out;

    const int gemm_sm = (128*132 + 128*72)*4;                           // 104448
    const int seq_sm  = (2*128*132 + 2*128*24 + 256 + 8*16*17)*4;       // 169472
    cudaFuncSetAttribute(k_gemm, cudaFuncAttributeMaxDynamicSharedMemorySize, gemm_sm);
    cudaFuncSetAttribute(k_seq,  cudaFuncAttributeMaxDynamicSharedMemorySize, seq_sm);

    k_embed<<<M_N, 128>>>(x, emb);
    k_repack<<<8713, 256>>>(wihl, whhl, bihl, bhhl, wihs, bihs, bhhs);
    dim3 g1(100, 32); k_gemm<<<g1, 256, gemm_sm>>>(0);
    dim3 g2(100, 4);  k_gemm<<<g2, 256, gemm_sm>>>(1);
    k_pe<<<100, 256>>>(wg, bg);
    k_seq<<<NG + 8, 256, seq_sm>>>(gum, wg, whhs);
    k_out<<<128, 128>>>(gum, wcls, bcls, out);
}

// round 15
// speedup vs baseline: 4.8584x; 1.2091x over previous
#include <cuda_runtime.h>
#include <cuda_fp16.h>
#include <cstdint>
#include <math.h>

#define S_T 100
#define B_N 128
#define D_N 512
#define SM_N 64
#define M_N (S_T*B_N)
#define EPSG 1e-20f
#define NC 136u
#define NG 128            // GEMM CTAs in k_seq

// ------------------------- device scratch (no allocs allowed) -------------
__device__ float    g_e[M_N*D_N];
__device__ __half   g_eh[M_N*D_N];            // fp16 e (GEMM A)
__device__ float    g_Xl[(size_t)M_N*2048];   // permuted cols (d*4+q)
__device__ float    g_Xs[M_N*256];
__device__ float    g_pe[M_N*2];
__device__ unsigned g_Wih_h[256*2048];        // half2 pairs (k,k+1) x permuted n
__device__ unsigned g_Whh_h[256*2048];        // half2 pairs (k,k+1) x permuted n
__device__ unsigned g_Wihs_h[256*256];        // half2 pairs (k,k+1) x natural n
__device__ float    g_bias_l[2048];
__device__ float    g_bias_s[256];
__device__ float    g_hlp[B_N*D_N];           // h_l'(t)
__device__ float    g_clp[B_N*D_N];           // c_l'(t) owner RMW
__device__ float    g_H[2][B_N*D_N];          // H(t-1) fp32 (mix/classifier source)
__device__ __half   g_Hh[2][B_N*D_N];         // H(t-1) fp16 (GEMM A)
__device__ float    g_hs[2][B_N*SM_N];
__device__ float    g_cs[2][B_N*SM_N];
__device__ float    g_ppart[2][NG*B_N*2];
__device__ unsigned g_bar;

// ------------------------- helpers ----------------------------------------
__device__ __forceinline__ void mmah(float* c, unsigned a0, unsigned a1, unsigned a2,
                                     unsigned a3, unsigned b0, unsigned b1){
    asm volatile(
      "mma.sync.aligned.m16n8k16.row.col.f32.f16.f16.f32 "
      "{%0,%1,%2,%3},{%4,%5,%6,%7},{%8,%9},{%0,%1,%2,%3};\n"
      : "+f"(c[0]), "+f"(c[1]), "+f"(c[2]), "+f"(c[3])
      : "r"(a0), "r"(a1), "r"(a2), "r"(a3), "r"(b0), "r"(b1));
}
__device__ __forceinline__ float sigf(float x){ return 1.f/(1.f+__expf(-x)); }
__device__ __forceinline__ unsigned packh2(float a, float b){
    __half2 h = __floats2half2_rn(a, b);
    return *reinterpret_cast<unsigned*>(&h);
}

__device__ __forceinline__ void cpa16(unsigned s, const void* g){
    asm volatile("cp.async.cg.shared.global [%0], [%1], 16;\n" :: "r"(s), "l"(g));
}
__device__ __forceinline__ void cpa_commit(){ asm volatile("cp.async.commit_group;\n" ::: "memory"); }
__device__ __forceinline__ void cpa_wait1(){ asm volatile("cp.async.wait_group 1;\n" ::: "memory"); }
__device__ __forceinline__ void cpa_wait0(){ asm volatile("cp.async.wait_group 0;\n" ::: "memory"); }

__device__ __forceinline__ void gbar(unsigned target){
    __syncthreads();
    if (threadIdx.x == 0){
        __threadfence();
        atomicAdd(&g_bar, 1u);
        unsigned v;
        while (true){
            asm volatile("ld.acquire.gpu.b32 %0, [%1];" : "=r"(v) : "l"(&g_bar) : "memory");
            if (v >= target) break;
            __nanosleep(32);
        }
    }
    __syncthreads();
}

// ------------------------- 1) embedding gather-sum (+barrier reset) --------
__global__ void k_embed(const int* __restrict__ x, const float* __restrict__ emb){
    int m = blockIdx.x;            // m = s*128 + b
    if (m == 0 && threadIdx.x == 0) g_bar = 0u;
    int s = m >> 7, b = m & 127;
    const int* codes = x + (b*S_T + s)*16;
    int d = threadIdx.x * 4;
    float4 acc = make_float4(0.f,0.f,0.f,0.f);
    #pragma unroll
    for (int n = 0; n < 16; n++){
        int c = codes[n];
        float4 v = *reinterpret_cast<const float4*>(emb + (size_t)c*D_N + d);
        acc.x += v.x; acc.y += v.y; acc.z += v.z; acc.w += v.w;
    }
    *reinterpret_cast<float4*>(g_e + (size_t)m*D_N + d) = acc;
    uint2 uu;
    uu.x = packh2(acc.x, acc.y);
    uu.y = packh2(acc.z, acc.w);
    *reinterpret_cast<uint2*>(&g_eh[(size_t)m*D_N + d]) = uu;
}

// ------------------------- 2) weight repack (fp16 pairs + biases) ----------
__global__ void k_repack(const float* __restrict__ wihl, const float* __restrict__ whhl,
                         const float* __restrict__ wihs,
                         const float* __restrict__ bihl, const float* __restrict__ bhhl,
                         const float* __restrict__ bihs, const float* __restrict__ bhhs){
    long idx = (long)blockIdx.x*256 + threadIdx.x;
    if (blockIdx.x < 2048){                      // Whh: [k2][n] pairs, n = d*4+q
        int k2 = (int)(idx >> 11), n = (int)(idx & 2047);
        int q = n & 3, dd = n >> 2;
        const float* src = whhl + (size_t)(q*512+dd)*512 + 2*k2;
        g_Whh_h[idx] = packh2(src[0], src[1]);
    } else if (blockIdx.x < 4096){               // Wih
        long i = idx - 2048L*256;
        int k2 = (int)(i >> 11), n = (int)(i & 2047);
        int q = n & 3, dd = n >> 2;
        const float* src = wihl + (size_t)(q*512+dd)*512 + 2*k2;
        g_Wih_h[i] = packh2(src[0], src[1]);
    } else if (blockIdx.x < 4352){               // Wihs: [k2][n] natural n
        long i = idx - 4096L*256;
        int k2 = (int)(i >> 8), n = (int)(i & 255);
        const float* src = wihs + (size_t)n*512 + 2*k2;
        g_Wihs_h[i] = packh2(src[0], src[1]);
    } else if (blockIdx.x < 4360){               // bias_l (permuted)
        int n = (int)(idx - 4352L*256);
        int q = n & 3, dd = n >> 2;
        g_bias_l[n] = bihl[q*512+dd] + bhhl[q*512+dd];
    } else {
        int n = threadIdx.x;
        g_bias_s[n] = bihs[n] + bhhs[n];
    }
}

// ------------------------- 3) input GEMMs (fp16 mma, occ=2) ----------------
// C[M,N] = e[M,512] @ W^T + bias. CTA tile 128x64, K chunks of 128.
__global__ void __launch_bounds__(256, 2) k_gemm(int mode){
    extern __shared__ unsigned smg[];
    unsigned* As = smg;                 // [128][68] words (136 halves/row)
    unsigned* Bs = smg + 128*68;        // [64][72] words (half2 pairs)
    const unsigned* Bp = mode ? g_Wihs_h : g_Wih_h;
    const float* bias  = mode ? g_bias_s : g_bias_l;
    float* C           = mode ? g_Xs    : g_Xl;
    const int N        = mode ? 256     : 2048;
    int bm = blockIdx.x, bn = blockIdx.y;
    int tid = threadIdx.x, wv = tid >> 5, lane = tid & 31;
    int fr = lane >> 2, fc = lane & 3;
    float acc[8][4];
    #pragma unroll
    for (int i = 0; i < 8; i++)
        #pragma unroll
        for (int j = 0; j < 4; j++) acc[i][j] = 0.f;
    for (int kc = 0; kc < 4; kc++){
        #pragma unroll
        for (int i = 0; i < 8; i++){
            int e = i*256 + tid;                       // 128 rows x 16 u4
            int r = e >> 4, c8 = e & 15;
            uint4 v = *reinterpret_cast<const uint4*>(
                &g_eh[(size_t)(bm*128 + r)*512 + kc*128 + c8*8]);
            *reinterpret_cast<uint4*>(reinterpret_cast<char*>(As) + r*272 + c8*16) = v;
        }
        #pragma unroll
        for (int i = 0; i < 4; i++){
            int e = i*256 + tid;                       // 64 rows x 16 u4
            int r = e >> 4, n4 = e & 15;
            uint4 v = *reinterpret_cast<const uint4*>(
                &Bp[(size_t)(kc*64 + r)*N + bn*64 + n4*4]);
            *reinterpret_cast<uint4*>(reinterpret_cast<char*>(Bs) + r*288 + n4*16) = v;
        }
        __syncthreads();
        #pragma unroll
        for (int ks = 0; ks < 8; ks++){
            int kk2 = ks*8;
            unsigned a0 = As[(wv*16 + fr    )*68 + kk2 + fc    ];
            unsigned a1 = As[(wv*16 + fr + 8)*68 + kk2 + fc    ];
            unsigned a2 = As[(wv*16 + fr    )*68 + kk2 + fc + 4];
            unsigned a3 = As[(wv*16 + fr + 8)*68 + kk2 + fc + 4];
            #pragma unroll
            for (int nf = 0; nf < 8; nf++){
                unsigned b0 = Bs[(kk2 + fc    )*72 + nf*8 + fr];
                unsigned b1 = Bs[(kk2 + fc + 4)*72 + nf*8 + fr];
                mmah(acc[nf], a0, a1, a2, a3, b0, b1);
            }
        }
        __syncthreads();
    }
    #pragma unroll
    for (int nf = 0; nf < 8; nf++){
        int row = bm*128 + wv*16 + fr;
        int col = bn*64 + nf*8 + fc*2;
        float b0 = bias[col], b1 = bias[col+1];
        C[(size_t)row*N + col]       = acc[nf][0] + b0;
        C[(size_t)row*N + col + 1]   = acc[nf][1] + b1;
        C[(size_t)(row+8)*N + col]   = acc[nf][2] + b0;
        C[(size_t)(row+8)*N + col+1] = acc[nf][3] + b1;
    }
}

// ------------------------- 4) e-part of gate logits ------------------------
__global__ void k_pe(const float* __restrict__ wg, const float* __restrict__ bg){
    int gw = blockIdx.x*8 + (threadIdx.x >> 5);
    int lane = threadIdx.x & 31;
    int stride = gridDim.x*8;
    for (int m = gw; m < M_N; m += stride){
        float s0 = 0.f, s1 = 0.f;
        for (int k = lane; k < 512; k += 32){
            float ev = g_e[(size_t)m*512 + k];
            s0 += ev*wg[k];
            s1 += ev*wg[1536 + k];
        }
        #pragma unroll
        for (int o = 16; o > 0; o >>= 1){
            s0 += __shfl_xor_sync(0xffffffffu, s0, o);
            s1 += __shfl_xor_sync(0xffffffffu, s1, o);
        }
        if (lane == 0){ g_pe[m*2] = s0 + bg[0]; g_pe[m*2+1] = s1 + bg[1]; }
    }
}

// ------------------------- 5) persistent scan kernel -----------------------
// CTAs 0..127: recurrent GEMM (16 permuted cols = 4 hidden dims each), fp16 mma.
// CTAs 128..135: small LSTM, state resident in smem.
__global__ void __launch_bounds__(256, 1) k_seq(const float* __restrict__ gum,
                                                const float* __restrict__ wg,
                                                const float* __restrict__ whs_g){
    extern __shared__ float sm[];
    int tid = threadIdx.x;
    unsigned bt = 0;

    if (blockIdx.x >= NG){
        float* whs = sm;                 // [256][65]
        float* hss = sm + 256*65;        // [16][64]
        float* css = hss + 1024;         // [16][64]
        int b0 = (blockIdx.x - NG)*16;
        for (int i = tid; i < 256*64; i += 256)
            whs[(i>>6)*65 + (i&63)] = whs_g[i];
        for (int i = tid; i < 1024; i += 256){ hss[i] = 0.f; css[i] = 0.f; }
        __syncthreads();
        int d = tid & 63, blb = tid >> 6;
        for (int t = 0; t < S_T; t++){
            int w = t & 1;
            bt += NC; gbar(bt);                    // barrier A
            float h2v[4], c2v[4];
            #pragma unroll
            for (int i = 0; i < 4; i++){
                int bl = blb + i*4;
                int b = b0 + bl;
                size_t xb = (size_t)(t*128 + b)*256;
                float gi = g_Xs[xb + d];
                float gf = g_Xs[xb + 64 + d];
                float gg = g_Xs[xb + 128 + d];
                float go = g_Xs[xb + 192 + d];
                for (int k = 0; k < 64; k++){
                    float h = hss[bl*64 + k];
                    gi += h*whs[(d      )*65 + k];
                    gf += h*whs[(64  + d)*65 + k];
                    gg += h*whs[(128 + d)*65 + k];
                    go += h*whs[(192 + d)*65 + k];
                }
                float cp = css[bl*64 + d];
                float c2 = sigf(gf)*cp + sigf(gi)*tanhf(gg);
                float h2 = sigf(go)*tanhf(c2);
                h2v[i] = h2; c2v[i] = c2;
                g_hs[w][b*64 + d] = h2;
                g_cs[w][b*64 + d] = c2;
            }
            __syncthreads();
            #pragma unroll
            for (int i = 0; i < 4; i++){
                int bl = blb + i*4;
                hss[bl*64 + d] = h2v[i];
                css[bl*64 + d] = c2v[i];
            }
            bt += NC; gbar(bt);                    // barrier B
        }
        return;
    }

    // word-layout: A: 2 x [128][68], B: 2 x [64][24], r0s, r1s, gsc
    const int ABUF = 128*68, BBUF = 64*24;
    unsigned* Asd = (unsigned*)sm;                   // 2 x ABUF
    unsigned* Bsd = (unsigned*)sm + 2*ABUF;          // 2 x BBUF
    float*    r0s = sm + 2*ABUF + 2*BBUF;            // [128]
    float*    r1s = r0s + 128;                       // [128]
    float*    gsc = r1s + 128;                       // 8 x [16][17]
    unsigned  smem_u32 = (unsigned)__cvta_generic_to_shared(sm);
    int ct = blockIdx.x;
    int wv = tid >> 5, lane = tid & 31;
    int fr = lane >> 2, fc = lane & 3;
    int dlo = ct*4;

    for (int t = 0; t < S_T; t++){
        int w = t & 1, rb = 1 - w;

        float xl[8];
        {
            size_t xbase = (size_t)(t*128)*2048 + ct*16;
            #pragma unroll
            for (int nf = 0; nf < 2; nf++){
                int rl = wv*16 + fr;
                int cl = nf*8 + fc*2;
                xl[nf*4+0] = g_Xl[xbase + (size_t)rl*2048 + cl];
                xl[nf*4+1] = g_Xl[xbase + (size_t)rl*2048 + cl + 1];
                xl[nf*4+2] = g_Xl[xbase + (size_t)(rl+8)*2048 + cl];
                xl[nf*4+3] = g_Xl[xbase + (size_t)(rl+8)*2048 + cl + 1];
            }
        }

        bt += NC; gbar(bt);                          // barrier A: ppart(t-1) ready

        // ---- phase 1: r(t-1) + H(t-1) slice ----
        if (t > 0){
            int b = tid >> 1, half = tid & 1;
            float y0 = 0.f, y1 = 0.f;
            #pragma unroll 8
            for (int j = half*64; j < half*64 + 64; j++){
                float2 pp = __ldcg((const float2*)&g_ppart[rb][(j*128 + b)*2]);
                y0 += pp.x; y1 += pp.y;
            }
            y0 += __shfl_xor_sync(0xffffffffu, y0, 1);
            y1 += __shfl_xor_sync(0xffffffffu, y1, 1);
            if (!half){
                y0 += g_pe[((t-1)*128 + b)*2];
                y1 += g_pe[((t-1)*128 + b)*2 + 1];
                float u0 = gum[((t-1)*128 + b)*2];
                float u1 = gum[((t-1)*128 + b)*2 + 1];
                y0 -= logf(-logf(u0 + EPSG) + EPSG);
                y1 -= logf(-logf(u1 + EPSG) + EPSG);
                float mx = fmaxf(y0, y1);
                float e0 = __expf(y0 - mx), e1 = __expf(y1 - mx);
                float r0 = e0/(e0 + e1);
                r0s[b] = r0; r1s[b] = 1.f - r0;
            }
            __syncthreads();
            #pragma unroll
            for (int i = 0; i < 2; i++){
                int e = i*256 + tid;                 // 128b x 4d
                int b2 = e >> 2, dloc = e & 3;
                int dg = dlo + dloc;
                float hl  = __ldcg(&g_hlp[b2*512 + dg]);
                float mix = (dg < 64) ? __ldcg(&g_hs[rb][b2*64 + dg])
                                      : __ldcg(&g_H[rb][b2*512 + dg]);
                float val = r0s[b2]*hl + r1s[b2]*mix;
                g_H[w][b2*512 + dg]  = val;
                g_Hh[w][b2*512 + dg] = __float2half_rn(val);
            }
        } else {
            #pragma unroll
            for (int i = 0; i < 2; i++){
                int e = i*256 + tid;
                int b2 = e >> 2, dloc = e & 3;
                g_H[w][b2*512 + dlo + dloc]  = 0.f;
                g_Hh[w][b2*512 + dlo + dloc] = __float2half_rn(0.f);
            }
        }

        bt += NC; gbar(bt);                          // barrier B: H(t-1) ready

        // ---- phase 2: GEMM over H(t-1) (cp.async double-buffered, fp16) ----
        float acc[2][4];
        #pragma unroll
        for (int i = 0; i < 2; i++)
            #pragma unroll
            for (int j = 0; j < 4; j++) acc[i][j] = 0.f;

        if (t > 0){
            const __half* Hb = &g_Hh[w][0];
            const unsigned* Wb = g_Whh_h;
            auto issue = [&](int kc, int q){
                #pragma unroll
                for (int i = 0; i < 8; i++){
                    int e = i*256 + tid;             // 128 rows x 16 u4 (8 halves each)
                    int b2 = e >> 4, c8 = e & 15;
                    unsigned dst = smem_u32 + (unsigned)(q*ABUF*4 + b2*272 + c8*16);
                    cpa16(dst, Hb + (size_t)b2*512 + kc*128 + c8*8);
                }
                {
                    int r = tid >> 2, n4 = tid & 3;  // 64 rows x 4 u4
                    unsigned dst = smem_u32 + (unsigned)((2*ABUF + q*BBUF)*4 + r*96 + n4*16);
                    cpa16(dst, Wb + (size_t)(kc*64 + r)*2048 + ct*16 + n4*4);
                }
                cpa_commit();
            };
            issue(0, 0);
            #pragma unroll
            for (int kc = 0; kc < 4; kc++){
                int q = kc & 1;
                if (kc < 3){ issue(kc+1, 1-q); cpa_wait1(); }
                else       { cpa_wait0(); }
                __syncthreads();
                unsigned* Aq = Asd + q*ABUF;
                unsigned* Bq = Bsd + q*BBUF;
                #pragma unroll
                for (int ks = 0; ks < 8; ks++){
                    int kk2 = ks*8;
                    unsigned a0 = Aq[(wv*16 + fr    )*68 + kk2 + fc    ];
                    unsigned a1 = Aq[(wv*16 + fr + 8)*68 + kk2 + fc    ];
                    unsigned a2 = Aq[(wv*16 + fr    )*68 + kk2 + fc + 4];
                    unsigned a3 = Aq[(wv*16 + fr + 8)*68 + kk2 + fc + 4];
                    #pragma unroll
                    for (int nf = 0; nf < 2; nf++){
                        unsigned b0 = Bq[(kk2 + fc    )*24 + nf*8 + fr];
                        unsigned b1 = Bq[(kk2 + fc + 4)*24 + nf*8 + fr];
                        mmah(acc[nf], a0, a1, a2, a3, b0, b1);
                    }
                }
                __syncthreads();
            }
        }

        // epilogue: gates -> smem, then cell per (b, dim)
        float* gw_ = gsc + wv*16*17;
        #pragma unroll
        for (int nf = 0; nf < 2; nf++){
            int cl = nf*8 + fc*2;
            gw_[(fr    )*17 + cl]   = acc[nf][0] + xl[nf*4+0];
            gw_[(fr    )*17 + cl+1] = acc[nf][1] + xl[nf*4+1];
            gw_[(fr + 8)*17 + cl]   = acc[nf][2] + xl[nf*4+2];
            gw_[(fr + 8)*17 + cl+1] = acc[nf][3] + xl[nf*4+3];
        }
        __syncwarp();
        #pragma unroll
        for (int i = 0; i < 2; i++){
            int idx = lane + 32*i;                   // 64 cells per warp (16b x 4d)
            int bl = idx >> 2, dloc = idx & 3;
            int b = wv*16 + bl;
            int dg = dlo + dloc;
            float gi = gw_[bl*17 + dloc*4 + 0];
            float gf = gw_[bl*17 + dloc*4 + 1];
            float gg = gw_[bl*17 + dloc*4 + 2];
            float go = gw_[bl*17 + dloc*4 + 3];
            float cp;
            if (t == 0) cp = 0.f;
            else {
                float cpl = g_clp[b*512 + dg];
                cp = (dg < 64) ? (r0s[b]*cpl + r1s[b]*__ldcg(&g_cs[rb][b*64 + dg])) : cpl;
            }
            float c2 = sigf(gf)*cp + sigf(gi)*tanhf(gg);
            float h2 = sigf(go)*tanhf(c2);
            g_clp[b*512 + dg] = c2;
            g_hlp[b*512 + dg] = h2;
            float p0 = h2*wg[512 + dg]        + c2*wg[1024 + dg];
            float p1 = h2*wg[1536 + 512 + dg] + c2*wg[1536 + 1024 + dg];
            #pragma unroll
            for (int o = 2; o > 0; o >>= 1){
                p0 += __shfl_xor_sync(0xffffffffu, p0, o);
                p1 += __shfl_xor_sync(0xffffffffu, p1, o);
            }
            if ((lane & 3) == 0){
                g_ppart[w][(ct*128 + b)*2]     = p0;
                g_ppart[w][(ct*128 + b)*2 + 1] = p1;
            }
        }
        __syncthreads();
    }
}

// ------------------------- 6) classifier epilogue --------------------------
__global__ void k_out(const float* __restrict__ gum, const float* __restrict__ wcls,
                      const float* __restrict__ bcls, float* __restrict__ out){
    __shared__ float y[2];
    __shared__ float red0[128], red1[128];
    int b = blockIdx.x, tid = threadIdx.x;
    if (tid < 2){
        float yy = g_pe[(99*128 + b)*2 + tid];
        for (int j = 0; j < NG; j++) yy += g_ppart[1][(j*128 + b)*2 + tid];
        float u = gum[(99*128 + b)*2 + tid];
        yy -= logf(-logf(u + EPSG) + EPSG);
        y[tid] = yy;
    }
    __syncthreads();
    float mx = fmaxf(y[0], y[1]);
    float e0 = __expf(y[0]-mx), e1 = __expf(y[1]-mx);
    float r0 = e0/(e0 + e1), r1 = 1.f - r0;
    float s0 = 0.f, s1 = 0.f;
    for (int d = tid; d < 512; d += 128){
        float hl  = g_hlp[b*512 + d];
        float mix = (d < 64) ? g_hs[1][b*64 + d] : g_H[1][b*512 + d];
        float h = fmaxf(r0*hl + r1*mix, 0.f);
        s0 += h*wcls[d];
        s1 += h*wcls[512 + d];
    }
    red0[tid] = s0; red1[tid] = s1;
    __syncthreads();
    for (int o = 64; o > 0; o >>= 1){
        if (tid < o){ red0[tid] += red0[tid+o]; red1[tid] += red1[tid+o]; }
        __syncthreads();
    }
    if (tid == 0){
        out[b*2]     = red0[0] + bcls[0];
        out[b*2 + 1] = red1[0] + bcls[1];
    }
}

// ------------------------- host --------------------------------------------
extern "C" void kernel_launch(void* const* d_in, const int* in_sizes, int n_in,
                              void* d_out, int out_size){
    const int*   x    = (const int*)  d_in[0];
    const float* gum  = (const float*)d_in[5];
    const float* emb  = (const float*)d_in[6];
    const float* wihl = (const float*)d_in[7];
    const float* whhl = (const float*)d_in[8];
    const float* bihl = (const float*)d_in[9];
    const float* bhhl = (const float*)d_in[10];
    const float* wihs = (const float*)d_in[11];
    const float* whhs = (const float*)d_in[12];
    const float* bihs = (const float*)d_in[13];
    const float* bhhs = (const float*)d_in[14];
    const float* wg   = (const float*)d_in[15];
    const float* bg   = (const float*)d_in[16];
    const float* wcls = (const float*)d_in[17];
    const float* bcls = (const float*)d_in[18];
    float* out = (float*)d_out;

    const int gemm_sm = (128*68 + 64*72)*4;                          // 53248
    const int seq_sm  = (2*128*68 + 2*64*24 + 256 + 8*16*17)*4;      // 87040
    cudaFuncSetAttribute(k_gemm, cudaFuncAttributeMaxDynamicSharedMemorySize, gemm_sm);
    cudaFuncSetAttribute(k_seq,  cudaFuncAttributeMaxDynamicSharedMemorySize, seq_sm);

    k_embed<<<M_N, 128>>>(x, emb);
    k_repack<<<4361, 256>>>(wihl, whhl, wihs, bihl, bhhl, bihs, bhhs);
    { dim3 g1(100, 32); k_gemm<<<g1, 256, gemm_sm>>>(0); }
    { dim3 g2(100, 4);  k_gemm<<<g2, 256, gemm_sm>>>(1); }
    k_pe<<<100, 256>>>(wg, bg);
    k_seq<<<NG + 8, 256, seq_sm>>>(gum, wg, whhs);
    k_out<<<128, 128>>>(gum, wcls, bcls, out);
}